// round 9
// baseline (speedup 1.0000x reference)
#include <cuda_runtime.h>
#include <cuda_fp16.h>
#include <cstdint>

// ---------------------------------------------------------------------------
// ConstrainedEnhancementModel on GB300 (ptxas target sm_103: no 'a' features).
// R9: GEMM6 in int8 IMMA (m16n8k32, s32 accum over full K — exact), operands
// quantized per-row (d2) / per-column (w6). Dequant fused into epilogue.
// Preamble: colmax fused with L1; w6 quant-pack spread across L2-L5 launches.
// ---------------------------------------------------------------------------

#define NB   512
#define NL   256
#define NF   32
#define NH   4096
#define NOUTCOL (NH * NF)          // 131072
#define LAST_KNOT ((NL - 1) * 16)  // 4080

// Scratch (device globals; allocation-free rule)
__device__ float  g_h1[512 * 1024];
__device__ float  g_h2[512 * 512];
__device__ float  g_fe[512 * 256];
__device__ float  g_d1[512 * 512];
__device__ float  g_d2f[512 * 1024];
__device__ int8_t g_d2q[32 * 512 * 32];              // [kt32][m][32k]
__device__ int8_t g_w6q[(size_t)1024 * 32 * 128 * 32]; // [nblk][kt32][128n][32k]
__device__ float  g_sa[512];                          // d2 row scales (max/127)
__device__ float  g_sbs[NOUTCOL];                     // w6 col scales (max/127)
__device__ float  g_sbinv[NOUTCOL];                   // 127/max

// ===========================================================================
// helpers
// ===========================================================================
__device__ __forceinline__ uint32_t smem_u32(const void* p) {
    uint32_t a;
    asm("{ .reg .u64 t; cvta.to.shared.u64 t, %1; cvt.u32.u64 %0, t; }"
        : "=r"(a) : "l"(p));
    return a;
}
__device__ __forceinline__ void cp16_cg(uint32_t dst, const void* src) {
    asm volatile("cp.async.cg.shared.global [%0], [%1], 16;"
                 :: "r"(dst), "l"(src) : "memory");
}
#define CP_COMMIT() asm volatile("cp.async.commit_group;" ::: "memory")
#define CP_WAIT6()  asm volatile("cp.async.wait_group 6;" ::: "memory")

__device__ __forceinline__ void mma_s8(int& c0, int& c1, int& c2, int& c3,
                                       uint32_t a0, uint32_t a1, uint32_t a2, uint32_t a3,
                                       uint32_t b0, uint32_t b1) {
    asm volatile(
        "mma.sync.aligned.m16n8k32.row.col.s32.s8.s8.s32 "
        "{%0,%1,%2,%3}, {%4,%5,%6,%7}, {%8,%9}, {%0,%1,%2,%3};"
        : "+r"(c0), "+r"(c1), "+r"(c2), "+r"(c3)
        : "r"(a0), "r"(a1), "r"(a2), "r"(a3), "r"(b0), "r"(b1));
}

__device__ __forceinline__ int8_t q8(float x, float inv) {
    float v = fminf(fmaxf(x * inv, -127.0f), 127.0f);
    return (int8_t)__float2int_rn(v);
}

// ===========================================================================
// Launch 1: L1 (blocks 0..127) + w6 column-max (blocks 128..639)
// ===========================================================================
__global__ void __launch_bounds__(256)
l1_colmax(const float* __restrict__ low, const float* __restrict__ w1,
          const float* __restrict__ b1, float* __restrict__ h1,
          const float* __restrict__ w6, float* __restrict__ sbs,
          float* __restrict__ sbinv)
{
    const int bx  = blockIdx.x;
    const int tid = threadIdx.x;

    if (bx < 128) {
        constexpr int BM = 64, BN = 64, BK = 16, TM = 4, TN = 4;
        constexpr int THREADS = 256;
        const int N = 1024, K = 8192;
        __shared__ float As[BK][BM + 4];
        __shared__ float Bs[BK][BN];

        const int bn = (bx & 15) * BN;
        const int bm = (bx >> 4) * BM;
        const int tx = tid % (BN / TN);
        const int ty = tid / (BN / TN);

        float acc[TM][TN];
#pragma unroll
        for (int i = 0; i < TM; i++)
#pragma unroll
            for (int j = 0; j < TN; j++) acc[i][j] = 0.0f;

        constexpr int AV = BK / 4, AT = BM * AV;
        constexpr int BV = BN / 4, BT = BK * BV;

        for (int k0 = 0; k0 < K; k0 += BK) {
            for (int i = tid; i < AT; i += THREADS) {
                int r = i / AV, c4 = (i % AV) * 4;
                float4 v = *reinterpret_cast<const float4*>(
                    low + (size_t)(bm + r) * K + k0 + c4);
                As[c4 + 0][r] = v.x; As[c4 + 1][r] = v.y;
                As[c4 + 2][r] = v.z; As[c4 + 3][r] = v.w;
            }
            for (int i = tid; i < BT; i += THREADS) {
                int r = i / BV, c4 = (i % BV) * 4;
                *reinterpret_cast<float4*>(&Bs[r][c4]) =
                    *reinterpret_cast<const float4*>(
                        w1 + (size_t)(k0 + r) * N + bn + c4);
            }
            __syncthreads();
#pragma unroll
            for (int kk = 0; kk < BK; kk++) {
                float ra[TM], rb[TN];
#pragma unroll
                for (int i = 0; i < TM; i += 4)
                    *reinterpret_cast<float4*>(&ra[i]) =
                        *reinterpret_cast<const float4*>(&As[kk][ty * TM + i]);
#pragma unroll
                for (int j = 0; j < TN; j += 4)
                    *reinterpret_cast<float4*>(&rb[j]) =
                        *reinterpret_cast<const float4*>(&Bs[kk][tx * TN + j]);
#pragma unroll
                for (int i = 0; i < TM; i++)
#pragma unroll
                    for (int j = 0; j < TN; j++)
                        acc[i][j] = fmaf(ra[i], rb[j], acc[i][j]);
            }
            __syncthreads();
        }
#pragma unroll
        for (int i = 0; i < TM; i++) {
            int row = bm + ty * TM + i;
#pragma unroll
            for (int j = 0; j < TN; j += 4) {
                int col = bn + tx * TN + j;
                float4 v;
                v.x = fmaxf(acc[i][j + 0] + b1[col + 0], 0.0f);
                v.y = fmaxf(acc[i][j + 1] + b1[col + 1], 0.0f);
                v.z = fmaxf(acc[i][j + 2] + b1[col + 2], 0.0f);
                v.w = fmaxf(acc[i][j + 3] + b1[col + 3], 0.0f);
                *reinterpret_cast<float4*>(h1 + (size_t)row * N + col) = v;
            }
        }
    } else {
        // column-max over w6[:, n] for 256 columns per block
        const int n = (bx - 128) * 256 + tid;
        const float* p = w6 + n;
        float m = 0.0f;
#pragma unroll 4
        for (int k = 0; k < 1024; k++)
            m = fmaxf(m, fabsf(p[(size_t)k * NOUTCOL]));
        sbs[n]   = m * (1.0f / 127.0f);
        sbinv[n] = (m > 0.0f) ? (127.0f / m) : 0.0f;
    }
}

// ===========================================================================
// Launches 2-5: small layer (runtime dims, 64x64x16 tiles) + w6 quant-pack.
//   layer blocks [0, nLayer), pack blocks [nLayer, nLayer + 8192)
//   pack block p (global): nblk = p>>5, kt = p&31; output tile 128n x 32k int8.
// ===========================================================================
__global__ void __launch_bounds__(256)
layer_pack(const float* __restrict__ A, const float* __restrict__ Bm,
           const float* __restrict__ bias, float* __restrict__ C,
           int M, int N, int K, int relu, int nLayer,
           const float* __restrict__ w6, const float* __restrict__ sbinv,
           int8_t* __restrict__ w6q, int packOfs)
{
    __shared__ __align__(16) char smbuf[32 * 133 * 4];
    const int bx  = blockIdx.x;
    const int tid = threadIdx.x;

    if (bx < nLayer) {
        constexpr int BM = 64, BN = 64, BK = 16, TM = 4, TN = 4;
        constexpr int THREADS = 256;
        float (*As)[BM + 4] = reinterpret_cast<float(*)[BM + 4]>(smbuf);
        float (*Bs)[BN] = reinterpret_cast<float(*)[BN]>(smbuf + BK * (BM + 4) * 4);

        const int gw = N / BN;
        const int bn = (bx % gw) * BN;
        const int bm = (bx / gw) * BM;
        const int tx = tid % (BN / TN);
        const int ty = tid / (BN / TN);

        float acc[TM][TN];
#pragma unroll
        for (int i = 0; i < TM; i++)
#pragma unroll
            for (int j = 0; j < TN; j++) acc[i][j] = 0.0f;

        constexpr int AV = BK / 4, AT = BM * AV;
        constexpr int BV = BN / 4, BT = BK * BV;

        for (int k0 = 0; k0 < K; k0 += BK) {
            for (int i = tid; i < AT; i += THREADS) {
                int r = i / AV, c4 = (i % AV) * 4;
                float4 v = *reinterpret_cast<const float4*>(
                    A + (size_t)(bm + r) * K + k0 + c4);
                As[c4 + 0][r] = v.x; As[c4 + 1][r] = v.y;
                As[c4 + 2][r] = v.z; As[c4 + 3][r] = v.w;
            }
            for (int i = tid; i < BT; i += THREADS) {
                int r = i / BV, c4 = (i % BV) * 4;
                *reinterpret_cast<float4*>(&Bs[r][c4]) =
                    *reinterpret_cast<const float4*>(
                        Bm + (size_t)(k0 + r) * N + bn + c4);
            }
            __syncthreads();
#pragma unroll
            for (int kk = 0; kk < BK; kk++) {
                float ra[TM], rb[TN];
#pragma unroll
                for (int i = 0; i < TM; i += 4)
                    *reinterpret_cast<float4*>(&ra[i]) =
                        *reinterpret_cast<const float4*>(&As[kk][ty * TM + i]);
#pragma unroll
                for (int j = 0; j < TN; j += 4)
                    *reinterpret_cast<float4*>(&rb[j]) =
                        *reinterpret_cast<const float4*>(&Bs[kk][tx * TN + j]);
#pragma unroll
                for (int i = 0; i < TM; i++)
#pragma unroll
                    for (int j = 0; j < TN; j++)
                        acc[i][j] = fmaf(ra[i], rb[j], acc[i][j]);
            }
            __syncthreads();
        }
#pragma unroll
        for (int i = 0; i < TM; i++) {
            int row = bm + ty * TM + i;
#pragma unroll
            for (int j = 0; j < TN; j += 4) {
                int col = bn + tx * TN + j;
                float4 v;
                v.x = acc[i][j + 0] + bias[col + 0];
                v.y = acc[i][j + 1] + bias[col + 1];
                v.z = acc[i][j + 2] + bias[col + 2];
                v.w = acc[i][j + 3] + bias[col + 3];
                if (relu) {
                    v.x = fmaxf(v.x, 0.0f); v.y = fmaxf(v.y, 0.0f);
                    v.z = fmaxf(v.z, 0.0f); v.w = fmaxf(v.w, 0.0f);
                }
                *reinterpret_cast<float4*>(C + (size_t)row * N + col) = v;
            }
        }
    } else {
        // ---- quant-pack one (nblk, kt) tile of w6 ----
        float (*ts)[133] = reinterpret_cast<float(*)[133]>(smbuf);
        const int p    = packOfs + (bx - nLayer);
        const int nblk = p >> 5;
        const int kt   = p & 31;

        for (int i = tid; i < 32 * 128; i += 256) {
            const int kk = i >> 7, n = i & 127;
            ts[kk][n] = w6[(size_t)(kt * 32 + kk) * NOUTCOL + nblk * 128 + n];
        }
        __syncthreads();

        const int n  = tid >> 1;
        const int kh = (tid & 1) * 16;
        const float inv = sbinv[nblk * 128 + n];
        int8_t tmp[16];
#pragma unroll
        for (int j = 0; j < 16; j++) tmp[j] = q8(ts[kh + j][n], inv);
        int8_t* dst = w6q + ((size_t)(nblk * 32 + kt) * 128 + n) * 32 + kh;
        *reinterpret_cast<uint4*>(dst) = *reinterpret_cast<const uint4*>(tmp);
    }
}

// ===========================================================================
// quant_d2: d2f fp32 [512][1024] -> per-row scale + int8 tiled [kt32][m][32]
// grid 512 (one block per row), 256 threads.
// ===========================================================================
__global__ void __launch_bounds__(256)
quant_d2(const float* __restrict__ d2f, int8_t* __restrict__ d2q,
         float* __restrict__ sa)
{
    __shared__ float wmax[8];
    const int r   = blockIdx.x;
    const int tid = threadIdx.x;

    float4 v = *reinterpret_cast<const float4*>(d2f + (size_t)r * 1024 + tid * 4);
    float m = fmaxf(fmaxf(fabsf(v.x), fabsf(v.y)), fmaxf(fabsf(v.z), fabsf(v.w)));
#pragma unroll
    for (int o = 16; o > 0; o >>= 1)
        m = fmaxf(m, __shfl_xor_sync(0xffffffffu, m, o));
    if ((tid & 31) == 0) wmax[tid >> 5] = m;
    __syncthreads();
    if (tid < 8) {
        float mm = wmax[tid];
#pragma unroll
        for (int o = 4; o > 0; o >>= 1)
            mm = fmaxf(mm, __shfl_xor_sync(0xffu, mm, o));
        if (tid == 0) { wmax[0] = mm; sa[r] = mm * (1.0f / 127.0f); }
    }
    __syncthreads();
    const float mx  = wmax[0];
    const float inv = (mx > 0.0f) ? (127.0f / mx) : 0.0f;

    int8_t q[4] = {q8(v.x, inv), q8(v.y, inv), q8(v.z, inv), q8(v.w, inv)};
    const int k0 = tid * 4;
    int8_t* dst = d2q + ((size_t)(k0 >> 5) * 512 + r) * 32 + (k0 & 31);
    *reinterpret_cast<uchar4*>(dst) = *reinterpret_cast<const uchar4*>(q);
}

// ===========================================================================
// GEMM6 int8: out = epilogue( dequant(d2q @ w6q^T) + b6 )
// CTA 128x128, 256 thr, 8 warps (2M x 4N), warp tile 64x32, K-step 32.
// 8-stage cp.async (dist 7). s32 accumulate over full K (exact), dequant once.
// SMEM pitch 48 B/row -> LDS.32 frag loads conflict-free (banks 12g+q).
// ===========================================================================
#define G6_STG    8
#define G6_PITCH  48                       // bytes per row (32 data + 16 pad)
#define G6_TILEB  (128 * G6_PITCH)         // 6144 bytes per stage tile
#define G6_NKT    32                       // 1024 / 32
#define G6_SMEMB  (2 * G6_STG * G6_TILEB + 1536)

__global__ void __launch_bounds__(256, 2)
gemm6_s8(const int8_t* __restrict__ Aq,   // d2q [32][512][32]
         const int8_t* __restrict__ Bq,   // w6q [1024][32][128][32]
         const float* __restrict__ sa,    // [512]
         const float* __restrict__ sb,    // [131072]
         const float* __restrict__ bias,
         const float* __restrict__ low,
         float* __restrict__ out)
{
    extern __shared__ char sm8[];
    char*  Asm = sm8;
    char*  Bsm = sm8 + G6_STG * G6_TILEB;
    float* ssa   = reinterpret_cast<float*>(sm8 + 2 * G6_STG * G6_TILEB);
    float* ssb   = ssa + 128;
    float* sbias = ssb + 128;

    const int tid  = threadIdx.x;
    const int wid  = tid >> 5;
    const int lane = tid & 31;
    const int g    = lane >> 2;
    const int q    = lane & 3;

    const int bm = blockIdx.x * 128;
    const int bn = blockIdx.y * 128;

    const int wm = (wid >> 2) * 64;
    const int wn = (wid & 3) * 32;

    if (tid < 128) {
        ssa[tid]   = sa[bm + tid];
        ssb[tid]   = sb[bn + tid];
        sbias[tid] = bias[bn + tid];
    }

    const uint32_t aBase = smem_u32(Asm);
    const uint32_t bBase = smem_u32(Bsm);

    // cp.async: each thread 1 A-chunk + 1 B-chunk (16B) per stage; tiles 4KB.
    const int row  = tid >> 1;
    const int half = tid & 1;
    const int8_t* aSrc = Aq + (size_t)bm * 32 + row * 32 + half * 16;      // +16384/kt
    const int8_t* bSrc = Bq + (size_t)blockIdx.y * 32 * 4096 + row * 32 + half * 16; // +4096/kt
    const uint32_t aDst = aBase + row * G6_PITCH + half * 16;
    const uint32_t bDst = bBase + row * G6_PITCH + half * 16;

#define G6_LOAD(s, kt)                                                 \
    do {                                                               \
        cp16_cg(aDst + (s) * G6_TILEB, aSrc + (size_t)(kt) * 16384);   \
        cp16_cg(bDst + (s) * G6_TILEB, bSrc + (size_t)(kt) * 4096);    \
    } while (0)

    G6_LOAD(0, 0); CP_COMMIT();
    G6_LOAD(1, 1); CP_COMMIT();
    G6_LOAD(2, 2); CP_COMMIT();
    G6_LOAD(3, 3); CP_COMMIT();
    G6_LOAD(4, 4); CP_COMMIT();
    G6_LOAD(5, 5); CP_COMMIT();
    G6_LOAD(6, 6); CP_COMMIT();

    int acc[4][4][4];
#pragma unroll
    for (int i = 0; i < 4; i++)
#pragma unroll
        for (int j = 0; j < 4; j++)
#pragma unroll
            for (int k = 0; k < 4; k++) acc[i][j][k] = 0;

    int s = 0, sl = 7;
    for (int kt = 0; kt < G6_NKT; kt++) {
        CP_WAIT6();
        __syncthreads();
        if (kt + 7 < G6_NKT) {
            G6_LOAD(sl, kt + 7);
        }
        CP_COMMIT();

        const uint32_t soA = aBase + (uint32_t)s * G6_TILEB;
        const uint32_t soB = bBase + (uint32_t)s * G6_TILEB;

        // B fragments: 4 n-tiles x 2 regs
        uint32_t bf[4][2];
#pragma unroll
        for (int nt = 0; nt < 4; nt++) {
            const uint32_t ba = soB + (wn + nt * 8 + g) * G6_PITCH + q * 4;
            asm volatile("ld.shared.b32 %0, [%1];" : "=r"(bf[nt][0]) : "r"(ba));
            asm volatile("ld.shared.b32 %0, [%1];" : "=r"(bf[nt][1]) : "r"(ba + 16));
        }
#pragma unroll
        for (int mt = 0; mt < 4; mt++) {
            const uint32_t aa = soA + (wm + mt * 16 + g) * G6_PITCH + q * 4;
            uint32_t a0, a1, a2, a3;
            asm volatile("ld.shared.b32 %0, [%1];" : "=r"(a0) : "r"(aa));
            asm volatile("ld.shared.b32 %0, [%1];" : "=r"(a1) : "r"(aa + 8 * G6_PITCH));
            asm volatile("ld.shared.b32 %0, [%1];" : "=r"(a2) : "r"(aa + 16));
            asm volatile("ld.shared.b32 %0, [%1];" : "=r"(a3) : "r"(aa + 8 * G6_PITCH + 16));
#pragma unroll
            for (int nt = 0; nt < 4; nt++)
                mma_s8(acc[mt][nt][0], acc[mt][nt][1],
                       acc[mt][nt][2], acc[mt][nt][3],
                       a0, a1, a2, a3, bf[nt][0], bf[nt][1]);
        }

        s  = (s + 1) & (G6_STG - 1);
        sl = (sl + 1) & (G6_STG - 1);
    }

    // ---- fused dequant + knot/interp epilogue (warp-uniform t) ----
    const int t   = (bn + wn) >> 5;
    const int rem = t & 15;
    const int seg = t >> 4;
    const bool knot  = (rem == 0);
    const bool inseg = (!knot) && (t < LAST_KNOT);
    const float alpha = (float)rem * 0.0625f;
    const int segB = (seg < NL - 1) ? seg + 1 : NL - 1;

#pragma unroll
    for (int mt = 0; mt < 4; mt++) {
#pragma unroll
        for (int h = 0; h < 2; h++) {
            const int rloc = wm + mt * 16 + g + h * 8;
            const int r = bm + rloc;
            const float sav = ssa[rloc];
            const float* lowr = low + (size_t)r * (NL * NF);
            float* outr = out + (size_t)r * NOUTCOL + bn + wn;
#pragma unroll
            for (int nt = 0; nt < 4; nt++) {
                const int f = nt * 8 + 2 * q;
                const int c0 = wn + f, c1 = c0 + 1;
                float dec0 = (float)acc[mt][nt][2 * h]     * sav * ssb[c0] + sbias[c0];
                float dec1 = (float)acc[mt][nt][2 * h + 1] * sav * ssb[c1] + sbias[c1];
                float2 la = *reinterpret_cast<const float2*>(lowr + seg  * NF + f);
                float2 lb = *reinterpret_cast<const float2*>(lowr + segB * NF + f);
                float lin0 = (1.0f - alpha) * la.x + alpha * lb.x;
                float lin1 = (1.0f - alpha) * la.y + alpha * lb.y;
                float r0 = knot ? la.x : (inseg ? 0.8f * lin0 + 0.2f * dec0 : dec0);
                float r1 = knot ? la.y : (inseg ? 0.8f * lin1 + 0.2f * dec1 : dec1);
                *reinterpret_cast<float2*>(outr + f) = make_float2(r0, r1);
            }
        }
    }
#undef G6_LOAD
}

// ---------------------------------------------------------------------------
extern "C" void kernel_launch(void* const* d_in, const int* in_sizes, int n_in,
                              void* d_out, int out_size)
{
    const float* low = (const float*)d_in[0];
    const float* w1  = (const float*)d_in[1];
    const float* b1  = (const float*)d_in[2];
    const float* w2  = (const float*)d_in[3];
    const float* b2  = (const float*)d_in[4];
    const float* w3  = (const float*)d_in[5];
    const float* b3  = (const float*)d_in[6];
    const float* w4  = (const float*)d_in[7];
    const float* b4  = (const float*)d_in[8];
    const float* w5  = (const float*)d_in[9];
    const float* b5  = (const float*)d_in[10];
    const float* w6  = (const float*)d_in[11];
    const float* b6  = (const float*)d_in[12];
    float* out = (float*)d_out;

    float *h1, *h2, *fe, *d1, *d2f, *sa, *sbs, *sbinv;
    int8_t *d2q, *w6q;
    cudaGetSymbolAddress((void**)&h1,    g_h1);
    cudaGetSymbolAddress((void**)&h2,    g_h2);
    cudaGetSymbolAddress((void**)&fe,    g_fe);
    cudaGetSymbolAddress((void**)&d1,    g_d1);
    cudaGetSymbolAddress((void**)&d2f,   g_d2f);
    cudaGetSymbolAddress((void**)&d2q,   g_d2q);
    cudaGetSymbolAddress((void**)&w6q,   g_w6q);
    cudaGetSymbolAddress((void**)&sa,    g_sa);
    cudaGetSymbolAddress((void**)&sbs,   g_sbs);
    cudaGetSymbolAddress((void**)&sbinv, g_sbinv);

    cudaFuncSetAttribute(gemm6_s8,
                         cudaFuncAttributeMaxDynamicSharedMemorySize, G6_SMEMB);

    // Launch 1: L1 + w6 column-max
    l1_colmax<<<128 + 512, 256>>>(low, w1, b1, h1, w6, sbs, sbinv);
    // Launches 2-5: small layers + w6 quant-pack (8192 tiles each, 32768 total)
    layer_pack<<<64 + 8192, 256>>>(h1, w2, b2, h2, 512, 512, 1024, 1, 64,
                                   w6, sbinv, w6q, 0);
    layer_pack<<<32 + 8192, 256>>>(h2, w3, b3, fe, 512, 256, 512, 0, 32,
                                   w6, sbinv, w6q, 8192);
    layer_pack<<<64 + 8192, 256>>>(fe, w4, b4, d1, 512, 512, 256, 1, 64,
                                   w6, sbinv, w6q, 16384);
    layer_pack<<<128 + 8192, 256>>>(d1, w5, b5, d2f, 512, 1024, 512, 1, 128,
                                    w6, sbinv, w6q, 24576);
    // Launch 6: quantize d2
    quant_d2<<<512, 256>>>(d2f, d2q, sa);
    // Launch 7: int8 GEMM6 + fused dequant/epilogue
    gemm6_s8<<<dim3(4, NOUTCOL / 128), 256, G6_SMEMB>>>(d2q, w6q, sa, sbs,
                                                        b6, low, out);
}

// round 10
// speedup vs baseline: 1.5230x; 1.5230x over previous
#include <cuda_runtime.h>
#include <cuda_fp16.h>
#include <cstdint>

// ---------------------------------------------------------------------------
// ConstrainedEnhancementModel on GB300 (ptxas target sm_103: no 'a' features).
// R10 = R7 (validated 1219us) + knot-column elimination:
//   gemm6 runs only the 3840 non-knot t's (N'=122880, -6.25%), since knot
//   columns (t%16==0) discard the GEMM result. Knot outputs are filled by a
//   trivial copy fused into the L1 launch. Legacy mma.sync is MAC-rate paced
//   (R8/R9 evidence), so gemm6 time scales directly with N.
// ---------------------------------------------------------------------------

#define NB   512
#define NL   256
#define NF   32
#define NH   4096
#define NOUTCOL (NH * NF)          // 131072
#define LAST_KNOT ((NL - 1) * 16)  // 4080
#define NPBLK 960                  // non-knot N-blocks (3840 t's / 4 per blk)

__device__ float  g_h1[512 * 1024];
__device__ float  g_h2[512 * 512];
__device__ float  g_fe[512 * 256];
__device__ float  g_d1[512 * 512];
__device__ __half g_d2h[512 * 1024];                // tiled [kt][m][16]
__device__ __half g_w6t[(size_t)NPBLK * 64 * 128 * 16]; // tiled [nblk'][kt][128][16]

// map non-knot index (0..3839) -> t (skips t%16==0)
__device__ __forceinline__ int map_t(int idx) {
    const int s = idx / 15;
    return s * 16 + 1 + (idx - s * 15);
}

// ===========================================================================
// helpers
// ===========================================================================
__device__ __forceinline__ uint32_t smem_u32(const void* p) {
    uint32_t a;
    asm("{ .reg .u64 t; cvta.to.shared.u64 t, %1; cvt.u32.u64 %0, t; }"
        : "=r"(a) : "l"(p));
    return a;
}
__device__ __forceinline__ void cp16_cg(uint32_t dst, const void* src) {
    asm volatile("cp.async.cg.shared.global [%0], [%1], 16;"
                 :: "r"(dst), "l"(src) : "memory");
}
#define CP_COMMIT() asm volatile("cp.async.commit_group;" ::: "memory")
#define CP_WAIT4()  asm volatile("cp.async.wait_group 4;" ::: "memory")

__device__ __forceinline__ void ldsm_x4(uint32_t& r0, uint32_t& r1,
                                        uint32_t& r2, uint32_t& r3, uint32_t addr) {
    asm volatile("ldmatrix.sync.aligned.m8n8.x4.shared.b16 {%0,%1,%2,%3}, [%4];"
                 : "=r"(r0), "=r"(r1), "=r"(r2), "=r"(r3) : "r"(addr));
}

__device__ __forceinline__ void mma_fp16(float& c0, float& c1, float& c2, float& c3,
                                         uint32_t a0, uint32_t a1, uint32_t a2, uint32_t a3,
                                         uint32_t b0, uint32_t b1) {
    asm volatile(
        "mma.sync.aligned.m16n8k16.row.col.f32.f16.f16.f32 "
        "{%0,%1,%2,%3}, {%4,%5,%6,%7}, {%8,%9}, {%0,%1,%2,%3};"
        : "+f"(c0), "+f"(c1), "+f"(c2), "+f"(c3)
        : "r"(a0), "r"(a1), "r"(a2), "r"(a3), "r"(b0), "r"(b1));
}

// ===========================================================================
// Launch 1: heterogeneous grid
//   [0,128):          L1 tiles  h1 = relu(low @ w1 + b1)
//   [128,640):        knot-fill out[b][16s][f] = low[b][s][f]
//   [640,640+61440):  pack w6 (non-knot cols) -> fp16 tiled [nblk'][kt][128][16]
// ===========================================================================
__global__ void __launch_bounds__(256)
l1_pack_fill(const float* __restrict__ low, const float* __restrict__ w1,
             const float* __restrict__ b1, float* __restrict__ h1,
             const float* __restrict__ w6, __half* __restrict__ w6t,
             float* __restrict__ out)
{
    const int bx  = blockIdx.x;
    const int tid = threadIdx.x;

    if (bx < 128) {
        constexpr int BM = 64, BN = 64, BK = 16, TM = 4, TN = 4;
        constexpr int THREADS = 256;
        const int N = 1024, K = 8192;
        __shared__ float As[BK][BM + 4];
        __shared__ float Bs[BK][BN];

        const int bn = (bx & 15) * BN;
        const int bm = (bx >> 4) * BM;
        const int tx = tid % (BN / TN);
        const int ty = tid / (BN / TN);

        float acc[TM][TN];
#pragma unroll
        for (int i = 0; i < TM; i++)
#pragma unroll
            for (int j = 0; j < TN; j++) acc[i][j] = 0.0f;

        constexpr int AV = BK / 4, AT = BM * AV;
        constexpr int BV = BN / 4, BT = BK * BV;

        for (int k0 = 0; k0 < K; k0 += BK) {
            for (int i = tid; i < AT; i += THREADS) {
                int r = i / AV, c4 = (i % AV) * 4;
                float4 v = *reinterpret_cast<const float4*>(
                    low + (size_t)(bm + r) * K + k0 + c4);
                As[c4 + 0][r] = v.x; As[c4 + 1][r] = v.y;
                As[c4 + 2][r] = v.z; As[c4 + 3][r] = v.w;
            }
            for (int i = tid; i < BT; i += THREADS) {
                int r = i / BV, c4 = (i % BV) * 4;
                *reinterpret_cast<float4*>(&Bs[r][c4]) =
                    *reinterpret_cast<const float4*>(
                        w1 + (size_t)(k0 + r) * N + bn + c4);
            }
            __syncthreads();
#pragma unroll
            for (int kk = 0; kk < BK; kk++) {
                float ra[TM], rb[TN];
#pragma unroll
                for (int i = 0; i < TM; i += 4)
                    *reinterpret_cast<float4*>(&ra[i]) =
                        *reinterpret_cast<const float4*>(&As[kk][ty * TM + i]);
#pragma unroll
                for (int j = 0; j < TN; j += 4)
                    *reinterpret_cast<float4*>(&rb[j]) =
                        *reinterpret_cast<const float4*>(&Bs[kk][tx * TN + j]);
#pragma unroll
                for (int i = 0; i < TM; i++)
#pragma unroll
                    for (int j = 0; j < TN; j++)
                        acc[i][j] = fmaf(ra[i], rb[j], acc[i][j]);
            }
            __syncthreads();
        }
#pragma unroll
        for (int i = 0; i < TM; i++) {
            int row = bm + ty * TM + i;
#pragma unroll
            for (int j = 0; j < TN; j += 4) {
                int col = bn + tx * TN + j;
                float4 v;
                v.x = fmaxf(acc[i][j + 0] + b1[col + 0], 0.0f);
                v.y = fmaxf(acc[i][j + 1] + b1[col + 1], 0.0f);
                v.z = fmaxf(acc[i][j + 2] + b1[col + 2], 0.0f);
                v.w = fmaxf(acc[i][j + 3] + b1[col + 3], 0.0f);
                *reinterpret_cast<float4*>(h1 + (size_t)row * N + col) = v;
            }
        }
    } else if (bx < 640) {
        // ---- knot-fill: out[b][16s][f] = low[b][s][f] ----
        const int b = bx - 128;
        const float* lb = low + (size_t)b * (NL * NF);
        float* ob = out + (size_t)b * NOUTCOL;
        for (int i = tid; i < NL * NF; i += 256) {
            const int s = i >> 5, f = i & 31;
            ob[s * 512 + f] = lb[i];
        }
    } else {
        // ---- pack one (nblk', kt) tile of w6 (non-knot columns) ----
        __shared__ __half ts[16][136];
        const int pid  = bx - 640;
        const int nblk = pid >> 6;     // 0..959
        const int kt   = pid & 63;     // 0..63

#pragma unroll
        for (int i = tid; i < 2048; i += 256) {
            const int k = i >> 7, n = i & 127;
            const int t = map_t(nblk * 4 + (n >> 5));
            ts[k][n] = __float2half(
                w6[(size_t)(kt * 16 + k) * NOUTCOL + t * 32 + (n & 31)]);
        }
        __syncthreads();

        const int n  = tid >> 1;
        const int kh = (tid & 1) * 8;
        __half tmp[8];
#pragma unroll
        for (int j = 0; j < 8; j++) tmp[j] = ts[kh + j][n];
        __half* dst = w6t + ((size_t)(nblk * 64 + kt) * 128 + n) * 16 + kh;
        *reinterpret_cast<uint4*>(dst) = *reinterpret_cast<const uint4*>(tmp);
    }
}

// ===========================================================================
// GEMM6 fp16 (R7 config): CTA 128x128, 8 warps (2M x 4N), warp tile 64x32,
// K-step 16, 6-stage cp.async (dist 5), ldmatrix.x4, pitch 24.
// N' = 122880 non-knot columns; grid (4, 960).
// ===========================================================================
#define G6_STG    6
#define G6_PITCH  24
#define G6_TILEH  (128 * G6_PITCH)
#define G6_TILEB  (G6_TILEH * 2)
#define G6_NKT    64
#define G6_SMEMB  (12 * G6_TILEB + 512)

__global__ void __launch_bounds__(256, 2)
gemm6_fp16(const __half* __restrict__ Ah,   // d2h tiled [64][512][16]
           const __half* __restrict__ Bt,   // w6t tiled [960][64][128][16]
           const float* __restrict__ bias,
           const float* __restrict__ low,
           float* __restrict__ out)
{
    extern __shared__ __half sm[];
    __half* Asm = sm;
    __half* Bsm = sm + G6_STG * G6_TILEH;
    float*  sbias = reinterpret_cast<float*>(sm + 2 * G6_STG * G6_TILEH);

    const int tid  = threadIdx.x;
    const int wid  = tid >> 5;
    const int lane = tid & 31;
    const int g    = lane >> 2;
    const int q    = lane & 3;

    const int bm = blockIdx.x * 128;

    const int wm = (wid >> 2) * 64;
    const int wn = (wid & 3) * 32;

    // bias: mapped global columns for this CTA's 4 non-knot t's
    if (tid < 128) {
        const int t = map_t(blockIdx.y * 4 + (tid >> 5));
        sbias[tid] = bias[t * 32 + (tid & 31)];
    }

    const uint32_t aBase = smem_u32(Asm);
    const uint32_t bBase = smem_u32(Bsm);

    const __half* aSrc = Ah + (size_t)bm * 16 + tid * 8;                // +8192/kt
    const __half* bSrc = Bt + (size_t)blockIdx.y * 64 * 2048 + tid * 8; // +2048/kt
    const uint32_t aDst = aBase + (tid >> 1) * 48 + (tid & 1) * 16;
    const uint32_t bDst = bBase + (tid >> 1) * 48 + (tid & 1) * 16;

#define G6_LOAD(s, kt)                                         \
    do {                                                       \
        cp16_cg(aDst + (s) * G6_TILEB, aSrc + (kt) * 8192);    \
        cp16_cg(bDst + (s) * G6_TILEB, bSrc + (kt) * 2048);    \
    } while (0)

    G6_LOAD(0, 0); CP_COMMIT();
    G6_LOAD(1, 1); CP_COMMIT();
    G6_LOAD(2, 2); CP_COMMIT();
    G6_LOAD(3, 3); CP_COMMIT();
    G6_LOAD(4, 4); CP_COMMIT();

    const int mi = lane >> 3;
    const int r8 = lane & 7;
    const uint32_t aLd = aBase +
        (uint32_t)(((wm + (mi & 1) * 8 + r8) * G6_PITCH + (mi >> 1) * 8) * 2);
    const uint32_t bLd = bBase +
        (uint32_t)(((wn + (mi >> 1) * 8 + r8) * G6_PITCH + (mi & 1) * 8) * 2);

    float acc[4][4][4];
#pragma unroll
    for (int i = 0; i < 4; i++)
#pragma unroll
        for (int j = 0; j < 4; j++)
#pragma unroll
            for (int k = 0; k < 4; k++) acc[i][j][k] = 0.0f;

    int s = 0, sl = G6_STG - 1;
    for (int kt = 0; kt < G6_NKT; kt++) {
        CP_WAIT4();
        __syncthreads();
        if (kt + 5 < G6_NKT) {
            G6_LOAD(sl, kt + 5);
        }
        CP_COMMIT();

        const uint32_t so = (uint32_t)s * G6_TILEB;

        uint32_t bf[4][2];
#pragma unroll
        for (int p = 0; p < 2; p++)
            ldsm_x4(bf[2 * p][0], bf[2 * p][1],
                    bf[2 * p + 1][0], bf[2 * p + 1][1],
                    bLd + p * (16 * G6_PITCH * 2) + so);

#pragma unroll
        for (int mt = 0; mt < 4; mt++) {
            uint32_t a0, a1, a2, a3;
            ldsm_x4(a0, a1, a2, a3, aLd + mt * (16 * G6_PITCH * 2) + so);
#pragma unroll
            for (int nt = 0; nt < 4; nt++)
                mma_fp16(acc[mt][nt][0], acc[mt][nt][1],
                         acc[mt][nt][2], acc[mt][nt][3],
                         a0, a1, a2, a3, bf[nt][0], bf[nt][1]);
        }

        s  = (s  + 1 == G6_STG) ? 0 : s  + 1;
        sl = (sl + 1 == G6_STG) ? 0 : sl + 1;
    }

    // ---- fused epilogue: warp covers one non-knot t ----
    const int idx = blockIdx.y * 4 + (wn >> 5);    // 0..3839
    const int seg = idx / 15;                      // = t>>4
    const int rem = idx - seg * 15 + 1;            // 1..15 (never knot)
    const int t   = seg * 16 + rem;
    const bool inseg = (t < LAST_KNOT);
    const float alpha = (float)rem * 0.0625f;
    const int segB = (seg < NL - 1) ? seg + 1 : NL - 1;

#pragma unroll
    for (int mt = 0; mt < 4; mt++) {
#pragma unroll
        for (int h = 0; h < 2; h++) {
            const int r = bm + wm + mt * 16 + g + h * 8;
            const float* lowr = low + (size_t)r * (NL * NF);
            float* outr = out + (size_t)r * NOUTCOL + t * 32;
#pragma unroll
            for (int nt = 0; nt < 4; nt++) {
                const int f = nt * 8 + 2 * q;
                float dec0 = acc[mt][nt][2 * h]     + sbias[wn + f];
                float dec1 = acc[mt][nt][2 * h + 1] + sbias[wn + f + 1];
                float2 la = *reinterpret_cast<const float2*>(lowr + seg  * NF + f);
                float2 lb = *reinterpret_cast<const float2*>(lowr + segB * NF + f);
                float lin0 = (1.0f - alpha) * la.x + alpha * lb.x;
                float lin1 = (1.0f - alpha) * la.y + alpha * lb.y;
                float r0 = inseg ? (0.8f * lin0 + 0.2f * dec0) : dec0;
                float r1 = inseg ? (0.8f * lin1 + 0.2f * dec1) : dec1;
                *reinterpret_cast<float2*>(outr + f) = make_float2(r0, r1);
            }
        }
    }
#undef G6_LOAD
}

// ===========================================================================
// Small-layer SIMT SGEMM; TILEDH=true stores fp16 tiled [col/16][row][16]
// ===========================================================================
template <int BM, int BN, int BK, int TM, int TN, bool RELU, bool TILEDH>
__global__ __launch_bounds__((BM / TM) * (BN / TN))
void sgemm_bias(const float* __restrict__ A, const float* __restrict__ Bm,
                const float* __restrict__ bias, void* __restrict__ Cv,
                int M, int N, int K)
{
    constexpr int THREADS = (BM / TM) * (BN / TN);
    __shared__ float As[BK][BM + 4];
    __shared__ float Bs[BK][BN];

    const int tid = threadIdx.x;
    const int bn  = blockIdx.x * BN;
    const int bm  = blockIdx.y * BM;
    const int tx  = tid % (BN / TN);
    const int ty  = tid / (BN / TN);

    float acc[TM][TN];
#pragma unroll
    for (int i = 0; i < TM; i++)
#pragma unroll
        for (int j = 0; j < TN; j++) acc[i][j] = 0.0f;

    constexpr int AV = BK / 4, AT = BM * AV;
    constexpr int BV = BN / 4, BT = BK * BV;

    for (int k0 = 0; k0 < K; k0 += BK) {
        for (int i = tid; i < AT; i += THREADS) {
            int r = i / AV, c4 = (i % AV) * 4;
            float4 v = *reinterpret_cast<const float4*>(
                A + (size_t)(bm + r) * K + k0 + c4);
            As[c4 + 0][r] = v.x; As[c4 + 1][r] = v.y;
            As[c4 + 2][r] = v.z; As[c4 + 3][r] = v.w;
        }
        for (int i = tid; i < BT; i += THREADS) {
            int r = i / BV, c4 = (i % BV) * 4;
            *reinterpret_cast<float4*>(&Bs[r][c4]) =
                *reinterpret_cast<const float4*>(
                    Bm + (size_t)(k0 + r) * N + bn + c4);
        }
        __syncthreads();

#pragma unroll
        for (int kk = 0; kk < BK; kk++) {
            float ra[TM], rb[TN];
#pragma unroll
            for (int i = 0; i < TM; i += 4)
                *reinterpret_cast<float4*>(&ra[i]) =
                    *reinterpret_cast<const float4*>(&As[kk][ty * TM + i]);
#pragma unroll
            for (int j = 0; j < TN; j += 4)
                *reinterpret_cast<float4*>(&rb[j]) =
                    *reinterpret_cast<const float4*>(&Bs[kk][tx * TN + j]);
#pragma unroll
            for (int i = 0; i < TM; i++)
#pragma unroll
                for (int j = 0; j < TN; j++)
                    acc[i][j] = fmaf(ra[i], rb[j], acc[i][j]);
        }
        __syncthreads();
    }

#pragma unroll
    for (int i = 0; i < TM; i++) {
        int row = bm + ty * TM + i;
#pragma unroll
        for (int j = 0; j < TN; j += 4) {
            int col = bn + tx * TN + j;
            float4 v;
            v.x = acc[i][j + 0] + bias[col + 0];
            v.y = acc[i][j + 1] + bias[col + 1];
            v.z = acc[i][j + 2] + bias[col + 2];
            v.w = acc[i][j + 3] + bias[col + 3];
            if (RELU) {
                v.x = fmaxf(v.x, 0.0f);
                v.y = fmaxf(v.y, 0.0f);
                v.z = fmaxf(v.z, 0.0f);
                v.w = fmaxf(v.w, 0.0f);
            }
            if (TILEDH) {
                __half* C = (__half*)Cv;
                __half* p = C + ((size_t)(col >> 4) * M + row) * 16 + (col & 15);
                __half2 h0 = __floats2half2_rn(v.x, v.y);
                __half2 h1 = __floats2half2_rn(v.z, v.w);
                *reinterpret_cast<__half2*>(p)     = h0;
                *reinterpret_cast<__half2*>(p + 2) = h1;
            } else {
                float* C = (float*)Cv;
                *reinterpret_cast<float4*>(C + (size_t)row * N + col) = v;
            }
        }
    }
}

// ---------------------------------------------------------------------------
extern "C" void kernel_launch(void* const* d_in, const int* in_sizes, int n_in,
                              void* d_out, int out_size)
{
    const float* low = (const float*)d_in[0];
    const float* w1  = (const float*)d_in[1];
    const float* b1  = (const float*)d_in[2];
    const float* w2  = (const float*)d_in[3];
    const float* b2  = (const float*)d_in[4];
    const float* w3  = (const float*)d_in[5];
    const float* b3  = (const float*)d_in[6];
    const float* w4  = (const float*)d_in[7];
    const float* b4  = (const float*)d_in[8];
    const float* w5  = (const float*)d_in[9];
    const float* b5  = (const float*)d_in[10];
    const float* w6  = (const float*)d_in[11];
    const float* b6  = (const float*)d_in[12];
    float* out = (float*)d_out;

    float  *h1, *h2, *fe, *d1;
    __half *d2h, *w6t;
    cudaGetSymbolAddress((void**)&h1,  g_h1);
    cudaGetSymbolAddress((void**)&h2,  g_h2);
    cudaGetSymbolAddress((void**)&fe,  g_fe);
    cudaGetSymbolAddress((void**)&d1,  g_d1);
    cudaGetSymbolAddress((void**)&d2h, g_d2h);
    cudaGetSymbolAddress((void**)&w6t, g_w6t);

    cudaFuncSetAttribute(gemm6_fp16,
                         cudaFuncAttributeMaxDynamicSharedMemorySize, G6_SMEMB);

    // Launch 1: L1 + knot-fill + pack_w6 (non-knot columns only)
    l1_pack_fill<<<128 + 512 + NPBLK * 64, 256>>>(low, w1, b1, h1, w6, w6t, out);
    // Launches 2-5: L2..L5
    sgemm_bias<64, 64, 16, 4, 4, true, false>
        <<<dim3(512 / 64, 512 / 64), 256>>>(h1, w2, b2, h2, 512, 512, 1024);
    sgemm_bias<64, 64, 16, 4, 4, false, false>
        <<<dim3(256 / 64, 512 / 64), 256>>>(h2, w3, b3, fe, 512, 256, 512);
    sgemm_bias<64, 64, 16, 4, 4, true, false>
        <<<dim3(512 / 64, 512 / 64), 256>>>(fe, w4, b4, d1, 512, 512, 256);
    sgemm_bias<64, 64, 16, 4, 4, true, true>
        <<<dim3(1024 / 64, 512 / 64), 256>>>(d1, w5, b5, d2h, 512, 1024, 512);
    // Launch 6: GEMM6 over non-knot columns (grid 4 x 960)
    gemm6_fp16<<<dim3(4, NPBLK), 256, G6_SMEMB>>>(d2h, w6t, b6, low, out);
}

// round 11
// speedup vs baseline: 2.2222x; 1.4591x over previous
#include <cuda_runtime.h>
#include <cuda_fp16.h>
#include <cstdint>

// ---------------------------------------------------------------------------
// ConstrainedEnhancementModel on GB300 (ptxas target sm_103: no 'a' features).
// R11 = R7 core with the preamble tensor-ized:
//   - L1 runs on fp16 mma.sync (inline fp32->fp16 cvt of low and w1),
//     B fragments via ldmatrix.x4.trans on k-major smem tiles.
//   - gemm6 keeps R7's A pipeline (cp.async, 6 stages) but converts w6 fp32
//     inline (LDG->cvt->STS, double-buffered) -- the pack kernel is gone.
// gemm6 remains MAC-wall-paced (R8/R9/R10 evidence); wins come from the
// preamble: launch1 ~190us (FFMA-bound) -> ~65us (MAC wall).
// ---------------------------------------------------------------------------

#define NB   512
#define NL   256
#define NF   32
#define NH   4096
#define NOUTCOL (NH * NF)          // 131072
#define LAST_KNOT ((NL - 1) * 16)  // 4080

__device__ float  g_h1[512 * 1024];
__device__ float  g_h2[512 * 512];
__device__ float  g_fe[512 * 256];
__device__ float  g_d1[512 * 512];
__device__ __half g_d2h[512 * 1024];                // tiled [kt][m][16]

// ===========================================================================
// helpers
// ===========================================================================
__device__ __forceinline__ uint32_t smem_u32(const void* p) {
    uint32_t a;
    asm("{ .reg .u64 t; cvta.to.shared.u64 t, %1; cvt.u32.u64 %0, t; }"
        : "=r"(a) : "l"(p));
    return a;
}
__device__ __forceinline__ void cp16_cg(uint32_t dst, const void* src) {
    asm volatile("cp.async.cg.shared.global [%0], [%1], 16;"
                 :: "r"(dst), "l"(src) : "memory");
}
#define CP_COMMIT() asm volatile("cp.async.commit_group;" ::: "memory")
#define CP_WAIT4()  asm volatile("cp.async.wait_group 4;" ::: "memory")

__device__ __forceinline__ void ldsm_x4(uint32_t& r0, uint32_t& r1,
                                        uint32_t& r2, uint32_t& r3, uint32_t addr) {
    asm volatile("ldmatrix.sync.aligned.m8n8.x4.shared.b16 {%0,%1,%2,%3}, [%4];"
                 : "=r"(r0), "=r"(r1), "=r"(r2), "=r"(r3) : "r"(addr));
}
__device__ __forceinline__ void ldsm_x4t(uint32_t& r0, uint32_t& r1,
                                         uint32_t& r2, uint32_t& r3, uint32_t addr) {
    asm volatile("ldmatrix.sync.aligned.m8n8.x4.trans.shared.b16 {%0,%1,%2,%3}, [%4];"
                 : "=r"(r0), "=r"(r1), "=r"(r2), "=r"(r3) : "r"(addr));
}

__device__ __forceinline__ void mma_fp16(float& c0, float& c1, float& c2, float& c3,
                                         uint32_t a0, uint32_t a1, uint32_t a2, uint32_t a3,
                                         uint32_t b0, uint32_t b1) {
    asm volatile(
        "mma.sync.aligned.m16n8k16.row.col.f32.f16.f16.f32 "
        "{%0,%1,%2,%3}, {%4,%5,%6,%7}, {%8,%9}, {%0,%1,%2,%3};"
        : "+f"(c0), "+f"(c1), "+f"(c2), "+f"(c3)
        : "r"(a0), "r"(a1), "r"(a2), "r"(a3), "r"(b0), "r"(b1));
}

// store float4 as 2 half2 (8 bytes) to shared
__device__ __forceinline__ void sts_cvt4(uint32_t addr, float4 v) {
    __half2 h01 = __floats2half2_rn(v.x, v.y);
    __half2 h23 = __floats2half2_rn(v.z, v.w);
    uint32_t u0 = *reinterpret_cast<uint32_t*>(&h01);
    uint32_t u1 = *reinterpret_cast<uint32_t*>(&h23);
    asm volatile("st.shared.v2.b32 [%0], {%1,%2};"
                 :: "r"(addr), "r"(u0), "r"(u1) : "memory");
}

// ===========================================================================
// L1 fp16 mma: h1 = relu(low @ w1 + b1).  M=512, N=1024, K=8192.
// CTA 64x64, grid 128 (1/SM). 8 warps (2M x 4N), warp tile 32x16.
// Per iter: k=32 (two MMA k-halves). Inline cvt of both operands; reg-staged
// LDG with distance 2; double-buffered smem.
// A smem: [64 m][40 halfs] (32k + 8 pad); B smem: k-major [32 k][72 halfs].
// ===========================================================================
#define L1_APITCH 40
#define L1_BPITCH 72
#define L1_ABUFH  (64 * L1_APITCH)   // 2560 halfs
#define L1_BBUFH  (32 * L1_BPITCH)   // 2304 halfs

__global__ void __launch_bounds__(256)
l1_mma(const float* __restrict__ low, const float* __restrict__ w1,
       const float* __restrict__ b1, float* __restrict__ h1)
{
    __shared__ __half As[2][L1_ABUFH];
    __shared__ __half Bs[2][L1_BBUFH];

    const int tid  = threadIdx.x;
    const int wid  = tid >> 5;
    const int lane = tid & 31;
    const int g    = lane >> 2;
    const int q    = lane & 3;

    const int bm = (blockIdx.x >> 4) * 64;   // 8 M blocks
    const int bn = (blockIdx.x & 15) * 64;   // 16 N blocks

    const int wm = (wid >> 2) * 32;          // 0/32
    const int wn = (wid & 3) * 16;           // 0..48

    const uint32_t aBase = smem_u32(&As[0][0]);
    const uint32_t bBase = smem_u32(&Bs[0][0]);

    // per-thread load coordinates (2 float4 per operand per iter)
    // A: 64 rows x 32 k fp32 = 512 chunks: m = c>>3, kc = c&7
    // B: 32 rows x 64 n fp32 = 512 chunks: k = c>>4, nc = c&15
    const int am0 = tid >> 3,  akc = tid & 7;        // + c1: m+32
    const int bk0 = tid >> 4,  bnc = tid & 15;       // + c1: k+16
    const float* aS = low + (size_t)(bm + am0) * 8192 + akc * 4;
    const float* bS = w1 + (size_t)bk0 * 1024 + bn + bnc * 4;
    const uint32_t aD0 = aBase + (uint32_t)(am0 * L1_APITCH + akc * 4) * 2;
    const uint32_t aD1 = aBase + (uint32_t)((am0 + 32) * L1_APITCH + akc * 4) * 2;
    const uint32_t bD0 = bBase + (uint32_t)(bk0 * L1_BPITCH + bnc * 4) * 2;
    const uint32_t bD1 = bBase + (uint32_t)((bk0 + 16) * L1_BPITCH + bnc * 4) * 2;

    float4 rA[2][2], rB[2][2];
#define L1_LDG(slot, it)                                                       \
    do {                                                                       \
        rA[slot][0] = *reinterpret_cast<const float4*>(aS + (it) * 32);        \
        rA[slot][1] = *reinterpret_cast<const float4*>(aS + 32 * 8192 + (it) * 32); \
        rB[slot][0] = *reinterpret_cast<const float4*>(bS + (size_t)(it) * 32 * 1024); \
        rB[slot][1] = *reinterpret_cast<const float4*>(bS + (size_t)((it) * 32 + 16) * 1024); \
    } while (0)

    L1_LDG(0, 0);
    L1_LDG(1, 1);

    // ldmatrix bases
    const int mi = lane >> 3;
    const int r8 = lane & 7;
    // A (row-major m x k), per mt and k-half h:
    const uint32_t aLd = aBase +
        (uint32_t)(((wm + (mi & 1) * 8 + r8) * L1_APITCH + (mi >> 1) * 8) * 2);
    // B (k-major), trans: lanes 0-15 rows k0-15, lanes 16-31 second n-octet
    const uint32_t bLd = bBase +
        (uint32_t)(((lane & 15) * L1_BPITCH + wn + (lane >> 4) * 8) * 2);

    float acc[2][2][4];
#pragma unroll
    for (int i = 0; i < 2; i++)
#pragma unroll
        for (int j = 0; j < 2; j++)
#pragma unroll
            for (int k = 0; k < 4; k++) acc[i][j][k] = 0.0f;

    for (int it = 0; it < 256; it++) {
        const int sl = it & 1;
        const uint32_t aOfs = (uint32_t)sl * (L1_ABUFH * 2);
        const uint32_t bOfs = (uint32_t)sl * (L1_BBUFH * 2);

        // cvt + STS data(it) from reg slot
        sts_cvt4(aD0 + aOfs, rA[sl][0]);
        sts_cvt4(aD1 + aOfs, rA[sl][1]);
        sts_cvt4(bD0 + bOfs, rB[sl][0]);
        sts_cvt4(bD1 + bOfs, rB[sl][1]);
        __syncthreads();

        // prefetch data(it+2) into the slot just drained
        if (it + 2 < 256) {
            L1_LDG(sl, it + 2);
        }

        // two k-halves
#pragma unroll
        for (int h = 0; h < 2; h++) {
            uint32_t b0, b1, b2, b3;
            ldsm_x4t(b0, b1, b2, b3,
                     bLd + bOfs + (uint32_t)(h * 16 * L1_BPITCH * 2));
#pragma unroll
            for (int mt = 0; mt < 2; mt++) {
                uint32_t a0, a1, a2, a3;
                ldsm_x4(a0, a1, a2, a3,
                        aLd + aOfs +
                        (uint32_t)((mt * 16 * L1_APITCH + h * 16) * 2));
                mma_fp16(acc[mt][0][0], acc[mt][0][1], acc[mt][0][2], acc[mt][0][3],
                         a0, a1, a2, a3, b0, b1);
                mma_fp16(acc[mt][1][0], acc[mt][1][1], acc[mt][1][2], acc[mt][1][3],
                         a0, a1, a2, a3, b2, b3);
            }
        }
        __syncthreads();
    }
#undef L1_LDG

    // epilogue: bias + relu, fp32 store
#pragma unroll
    for (int mt = 0; mt < 2; mt++) {
#pragma unroll
        for (int h8 = 0; h8 < 2; h8++) {
            const int row = bm + wm + mt * 16 + g + h8 * 8;
#pragma unroll
            for (int nt = 0; nt < 2; nt++) {
                const int col = bn + wn + nt * 8 + 2 * q;
                float v0 = fmaxf(acc[mt][nt][2 * h8]     + b1[col],     0.0f);
                float v1 = fmaxf(acc[mt][nt][2 * h8 + 1] + b1[col + 1], 0.0f);
                *reinterpret_cast<float2*>(h1 + (size_t)row * 1024 + col) =
                    make_float2(v0, v1);
            }
        }
    }
}

// ===========================================================================
// GEMM6 fp16 (R7 core): out = epilogue( d2h @ w6^T + b6 ).
// CTA 128x128, 8 warps (2M x 4N), warp tile 64x32, K-step 16.
// A: cp.async 6 stages (dist 5) from tiled d2h (validated R7).
// B: INLINE fp32->fp16 (LDG + cvt + STS into k-major double buffer),
//    fragments via ldmatrix.x4.trans. No pack kernel.
// ===========================================================================
#define G6_STG    6
#define G6_PITCH  24
#define G6_TILEH  (128 * G6_PITCH)         // 3072 halfs per A stage
#define G6_TILEB  (G6_TILEH * 2)           // 6144 B
#define G6_BPITCH 136
#define G6_BBUFH  (16 * G6_BPITCH)         // 2176 halfs
#define G6_BBUFB  (G6_BBUFH * 2)           // 4352 B
#define G6_NKT    64
#define G6_SMEMB  (G6_STG * G6_TILEB + 2 * G6_BBUFB + 512)   // 46080 B

__global__ void __launch_bounds__(256, 2)
gemm6_fp16(const __half* __restrict__ Ah,   // d2h tiled [64][512][16]
           const float* __restrict__ w6,    // fp32 [1024][131072]
           const float* __restrict__ bias,
           const float* __restrict__ low,
           float* __restrict__ out)
{
    extern __shared__ __half sm[];
    __half* Asm = sm;                             // 6 stages
    __half* Bsm = sm + G6_STG * G6_TILEH;         // 2 buffers
    float*  sbias = reinterpret_cast<float*>(sm + G6_STG * G6_TILEH + 2 * G6_BBUFH);

    const int tid  = threadIdx.x;
    const int wid  = tid >> 5;
    const int lane = tid & 31;
    const int g    = lane >> 2;
    const int q    = lane & 3;

    const int bm = blockIdx.x * 128;   // 4 M-blocks fastest -> share w6 in L2
    const int bn = blockIdx.y * 128;

    const int wm = (wid >> 2) * 64;
    const int wn = (wid & 3) * 32;

    if (tid < 128) sbias[tid] = bias[bn + tid];

    const uint32_t aBase = smem_u32(Asm);
    const uint32_t bBase = smem_u32(Bsm);

    // ---- A: cp.async (R7-identical) ----
    const __half* aSrc = Ah + (size_t)bm * 16 + tid * 8;   // +8192 halfs per kt
    const uint32_t aDst = aBase + (tid >> 1) * 48 + (tid & 1) * 16;
#define G6_LOADA(s, kt) cp16_cg(aDst + (s) * G6_TILEB, aSrc + (kt) * 8192)

    G6_LOADA(0, 0); CP_COMMIT();
    G6_LOADA(1, 1); CP_COMMIT();
    G6_LOADA(2, 2); CP_COMMIT();
    G6_LOADA(3, 3); CP_COMMIT();
    G6_LOADA(4, 4); CP_COMMIT();

    // ---- B: direct fp32 loads, 2 float4 per thread per kt ----
    // tile 16 k-rows x 128 n fp32: c0 = tid (k=tid>>5, nc=tid&31), c1 = +256
    const int bk0 = tid >> 5;          // 0..7 (c1 -> +8)
    const int bnc = tid & 31;
    const float* bS = w6 + (size_t)bk0 * NOUTCOL + bn + bnc * 4;
    const uint32_t bD0 = bBase + (uint32_t)(bk0 * G6_BPITCH + bnc * 4) * 2;
    const uint32_t bD1 = bBase + (uint32_t)((bk0 + 8) * G6_BPITCH + bnc * 4) * 2;

    float4 rb0, rb1;
#define G6_LDGB(kt)                                                            \
    do {                                                                       \
        rb0 = *reinterpret_cast<const float4*>(bS + (size_t)(kt) * 16 * NOUTCOL); \
        rb1 = *reinterpret_cast<const float4*>(bS + (size_t)((kt) * 16 + 8) * NOUTCOL); \
    } while (0)

    G6_LDGB(0);

    // ldmatrix bases (A mapping validated R5-R7; B via trans on k-major)
    const int mi = lane >> 3;
    const int r8 = lane & 7;
    const uint32_t aLd = aBase +
        (uint32_t)(((wm + (mi & 1) * 8 + r8) * G6_PITCH + (mi >> 1) * 8) * 2);
    const uint32_t bLd = bBase +
        (uint32_t)(((lane & 15) * G6_BPITCH + wn + (lane >> 4) * 8) * 2);

    float acc[4][4][4];
#pragma unroll
    for (int i = 0; i < 4; i++)
#pragma unroll
        for (int j = 0; j < 4; j++)
#pragma unroll
            for (int k = 0; k < 4; k++) acc[i][j][k] = 0.0f;

    int s = 0, sl = G6_STG - 1;
    for (int kt = 0; kt < G6_NKT; kt++) {
        const uint32_t bOfs = (uint32_t)(kt & 1) * G6_BBUFB;

        // cvt + STS B(kt)
        sts_cvt4(bD0 + bOfs, rb0);
        sts_cvt4(bD1 + bOfs, rb1);

        // prefetch B(kt+1)
        if (kt + 1 < G6_NKT) {
            G6_LDGB(kt + 1);
        }

        CP_WAIT4();
        __syncthreads();
        if (kt + 5 < G6_NKT) {
            G6_LOADA(sl, kt + 5);
        }
        CP_COMMIT();

        const uint32_t so = (uint32_t)s * G6_TILEB;

        // B fragments: 2 x ldsm.x4.trans cover 4 n-octets x k16
        uint32_t bf[4][2];
        ldsm_x4t(bf[0][0], bf[0][1], bf[1][0], bf[1][1], bLd + bOfs);
        ldsm_x4t(bf[2][0], bf[2][1], bf[3][0], bf[3][1], bLd + bOfs + 32);

#pragma unroll
        for (int mt = 0; mt < 4; mt++) {
            uint32_t a0, a1, a2, a3;
            ldsm_x4(a0, a1, a2, a3, aLd + mt * (16 * G6_PITCH * 2) + so);
#pragma unroll
            for (int nt = 0; nt < 4; nt++)
                mma_fp16(acc[mt][nt][0], acc[mt][nt][1],
                         acc[mt][nt][2], acc[mt][nt][3],
                         a0, a1, a2, a3, bf[nt][0], bf[nt][1]);
        }

        s  = (s  + 1 == G6_STG) ? 0 : s  + 1;
        sl = (sl + 1 == G6_STG) ? 0 : sl + 1;
    }
#undef G6_LOADA
#undef G6_LDGB

    // ---- fused epilogue (warp-uniform t) ----
    const int t   = (bn + wn) >> 5;
    const int rem = t & 15;
    const int seg = t >> 4;
    const bool knot  = (rem == 0);
    const bool inseg = (!knot) && (t < LAST_KNOT);
    const float alpha = (float)rem * 0.0625f;
    const int segB = (seg < NL - 1) ? seg + 1 : NL - 1;

#pragma unroll
    for (int mt = 0; mt < 4; mt++) {
#pragma unroll
        for (int h = 0; h < 2; h++) {
            const int r = bm + wm + mt * 16 + g + h * 8;
            const float* lowr = low + (size_t)r * (NL * NF);
            float* outr = out + (size_t)r * NOUTCOL + bn + wn;
#pragma unroll
            for (int nt = 0; nt < 4; nt++) {
                const int f = nt * 8 + 2 * q;
                float dec0 = acc[mt][nt][2 * h]     + sbias[wn + f];
                float dec1 = acc[mt][nt][2 * h + 1] + sbias[wn + f + 1];
                float2 la = *reinterpret_cast<const float2*>(lowr + seg  * NF + f);
                float2 lb = *reinterpret_cast<const float2*>(lowr + segB * NF + f);
                float lin0 = (1.0f - alpha) * la.x + alpha * lb.x;
                float lin1 = (1.0f - alpha) * la.y + alpha * lb.y;
                float r0 = knot ? la.x : (inseg ? 0.8f * lin0 + 0.2f * dec0 : dec0);
                float r1 = knot ? la.y : (inseg ? 0.8f * lin1 + 0.2f * dec1 : dec1);
                *reinterpret_cast<float2*>(outr + f) = make_float2(r0, r1);
            }
        }
    }
}

// ===========================================================================
// Small-layer SIMT SGEMM; TILEDH=true stores fp16 tiled [col/16][row][16]
// ===========================================================================
template <int BM, int BN, int BK, int TM, int TN, bool RELU, bool TILEDH>
__global__ __launch_bounds__((BM / TM) * (BN / TN))
void sgemm_bias(const float* __restrict__ A, const float* __restrict__ Bm,
                const float* __restrict__ bias, void* __restrict__ Cv,
                int M, int N, int K)
{
    constexpr int THREADS = (BM / TM) * (BN / TN);
    __shared__ float As[BK][BM + 4];
    __shared__ float Bs[BK][BN];

    const int tid = threadIdx.x;
    const int bn  = blockIdx.x * BN;
    const int bm  = blockIdx.y * BM;
    const int tx  = tid % (BN / TN);
    const int ty  = tid / (BN / TN);

    float acc[TM][TN];
#pragma unroll
    for (int i = 0; i < TM; i++)
#pragma unroll
        for (int j = 0; j < TN; j++) acc[i][j] = 0.0f;

    constexpr int AV = BK / 4, AT = BM * AV;
    constexpr int BV = BN / 4, BT = BK * BV;

    for (int k0 = 0; k0 < K; k0 += BK) {
        for (int i = tid; i < AT; i += THREADS) {
            int r = i / AV, c4 = (i % AV) * 4;
            float4 v = *reinterpret_cast<const float4*>(
                A + (size_t)(bm + r) * K + k0 + c4);
            As[c4 + 0][r] = v.x; As[c4 + 1][r] = v.y;
            As[c4 + 2][r] = v.z; As[c4 + 3][r] = v.w;
        }
        for (int i = tid; i < BT; i += THREADS) {
            int r = i / BV, c4 = (i % BV) * 4;
            *reinterpret_cast<float4*>(&Bs[r][c4]) =
                *reinterpret_cast<const float4*>(
                    Bm + (size_t)(k0 + r) * N + bn + c4);
        }
        __syncthreads();

#pragma unroll
        for (int kk = 0; kk < BK; kk++) {
            float ra[TM], rb[TN];
#pragma unroll
            for (int i = 0; i < TM; i += 4)
                *reinterpret_cast<float4*>(&ra[i]) =
                    *reinterpret_cast<const float4*>(&As[kk][ty * TM + i]);
#pragma unroll
            for (int j = 0; j < TN; j += 4)
                *reinterpret_cast<float4*>(&rb[j]) =
                    *reinterpret_cast<const float4*>(&Bs[kk][tx * TN + j]);
#pragma unroll
            for (int i = 0; i < TM; i++)
#pragma unroll
                for (int j = 0; j < TN; j++)
                    acc[i][j] = fmaf(ra[i], rb[j], acc[i][j]);
        }
        __syncthreads();
    }

#pragma unroll
    for (int i = 0; i < TM; i++) {
        int row = bm + ty * TM + i;
#pragma unroll
        for (int j = 0; j < TN; j += 4) {
            int col = bn + tx * TN + j;
            float4 v;
            v.x = acc[i][j + 0] + bias[col + 0];
            v.y = acc[i][j + 1] + bias[col + 1];
            v.z = acc[i][j + 2] + bias[col + 2];
            v.w = acc[i][j + 3] + bias[col + 3];
            if (RELU) {
                v.x = fmaxf(v.x, 0.0f);
                v.y = fmaxf(v.y, 0.0f);
                v.z = fmaxf(v.z, 0.0f);
                v.w = fmaxf(v.w, 0.0f);
            }
            if (TILEDH) {
                __half* C = (__half*)Cv;
                __half* p = C + ((size_t)(col >> 4) * M + row) * 16 + (col & 15);
                __half2 h0 = __floats2half2_rn(v.x, v.y);
                __half2 h1 = __floats2half2_rn(v.z, v.w);
                *reinterpret_cast<__half2*>(p)     = h0;
                *reinterpret_cast<__half2*>(p + 2) = h1;
            } else {
                float* C = (float*)Cv;
                *reinterpret_cast<float4*>(C + (size_t)row * N + col) = v;
            }
        }
    }
}

// ---------------------------------------------------------------------------
extern "C" void kernel_launch(void* const* d_in, const int* in_sizes, int n_in,
                              void* d_out, int out_size)
{
    const float* low = (const float*)d_in[0];
    const float* w1  = (const float*)d_in[1];
    const float* b1  = (const float*)d_in[2];
    const float* w2  = (const float*)d_in[3];
    const float* b2  = (const float*)d_in[4];
    const float* w3  = (const float*)d_in[5];
    const float* b3  = (const float*)d_in[6];
    const float* w4  = (const float*)d_in[7];
    const float* b4  = (const float*)d_in[8];
    const float* w5  = (const float*)d_in[9];
    const float* b5  = (const float*)d_in[10];
    const float* w6  = (const float*)d_in[11];
    const float* b6  = (const float*)d_in[12];
    float* out = (float*)d_out;

    float  *h1, *h2, *fe, *d1;
    __half *d2h;
    cudaGetSymbolAddress((void**)&h1,  g_h1);
    cudaGetSymbolAddress((void**)&h2,  g_h2);
    cudaGetSymbolAddress((void**)&fe,  g_fe);
    cudaGetSymbolAddress((void**)&d1,  g_d1);
    cudaGetSymbolAddress((void**)&d2h, g_d2h);

    cudaFuncSetAttribute(gemm6_fp16,
                         cudaFuncAttributeMaxDynamicSharedMemorySize, G6_SMEMB);

    // Launch 1: L1 via fp16 mma (inline cvt of low, w1)
    l1_mma<<<128, 256>>>(low, w1, b1, h1);
    // Launches 2-5: L2..L5 (fp32 SIMT; L5 emits fp16 tiled d2h)
    sgemm_bias<64, 64, 16, 4, 4, true, false>
        <<<dim3(512 / 64, 512 / 64), 256>>>(h1, w2, b2, h2, 512, 512, 1024);
    sgemm_bias<64, 64, 16, 4, 4, false, false>
        <<<dim3(256 / 64, 512 / 64), 256>>>(h2, w3, b3, fe, 512, 256, 512);
    sgemm_bias<64, 64, 16, 4, 4, true, false>
        <<<dim3(512 / 64, 512 / 64), 256>>>(fe, w4, b4, d1, 512, 512, 256);
    sgemm_bias<64, 64, 16, 4, 4, true, true>
        <<<dim3(1024 / 64, 512 / 64), 256>>>(d1, w5, b5, d2h, 512, 1024, 512);
    // Launch 6: GEMM6 (inline w6 conversion; captured by ncu -s 5 -c 1)
    gemm6_fp16<<<dim3(4, NOUTCOL / 128), 256, G6_SMEMB>>>(d2h, w6, b6, low, out);
}

// round 12
// speedup vs baseline: 2.4322x; 1.0945x over previous
#include <cuda_runtime.h>
#include <cuda_fp16.h>
#include <cstdint>

// ---------------------------------------------------------------------------
// ConstrainedEnhancementModel on GB300 (ptxas target sm_103: no 'a' features).
// R12 = R11 (870us) + (1) gemm6 B-prefetch distance 2, (2) small layers
// re-tiled for >=128 CTAs (L2/L4: 64x32, L3: 32x32).
// ---------------------------------------------------------------------------

#define NB   512
#define NL   256
#define NF   32
#define NH   4096
#define NOUTCOL (NH * NF)          // 131072
#define LAST_KNOT ((NL - 1) * 16)  // 4080

__device__ float  g_h1[512 * 1024];
__device__ float  g_h2[512 * 512];
__device__ float  g_fe[512 * 256];
__device__ float  g_d1[512 * 512];
__device__ __half g_d2h[512 * 1024];                // tiled [kt][m][16]

// ===========================================================================
// helpers
// ===========================================================================
__device__ __forceinline__ uint32_t smem_u32(const void* p) {
    uint32_t a;
    asm("{ .reg .u64 t; cvta.to.shared.u64 t, %1; cvt.u32.u64 %0, t; }"
        : "=r"(a) : "l"(p));
    return a;
}
__device__ __forceinline__ void cp16_cg(uint32_t dst, const void* src) {
    asm volatile("cp.async.cg.shared.global [%0], [%1], 16;"
                 :: "r"(dst), "l"(src) : "memory");
}
#define CP_COMMIT() asm volatile("cp.async.commit_group;" ::: "memory")
#define CP_WAIT4()  asm volatile("cp.async.wait_group 4;" ::: "memory")

__device__ __forceinline__ void ldsm_x4(uint32_t& r0, uint32_t& r1,
                                        uint32_t& r2, uint32_t& r3, uint32_t addr) {
    asm volatile("ldmatrix.sync.aligned.m8n8.x4.shared.b16 {%0,%1,%2,%3}, [%4];"
                 : "=r"(r0), "=r"(r1), "=r"(r2), "=r"(r3) : "r"(addr));
}
__device__ __forceinline__ void ldsm_x4t(uint32_t& r0, uint32_t& r1,
                                         uint32_t& r2, uint32_t& r3, uint32_t addr) {
    asm volatile("ldmatrix.sync.aligned.m8n8.x4.trans.shared.b16 {%0,%1,%2,%3}, [%4];"
                 : "=r"(r0), "=r"(r1), "=r"(r2), "=r"(r3) : "r"(addr));
}

__device__ __forceinline__ void mma_fp16(float& c0, float& c1, float& c2, float& c3,
                                         uint32_t a0, uint32_t a1, uint32_t a2, uint32_t a3,
                                         uint32_t b0, uint32_t b1) {
    asm volatile(
        "mma.sync.aligned.m16n8k16.row.col.f32.f16.f16.f32 "
        "{%0,%1,%2,%3}, {%4,%5,%6,%7}, {%8,%9}, {%0,%1,%2,%3};"
        : "+f"(c0), "+f"(c1), "+f"(c2), "+f"(c3)
        : "r"(a0), "r"(a1), "r"(a2), "r"(a3), "r"(b0), "r"(b1));
}

__device__ __forceinline__ void sts_cvt4(uint32_t addr, float4 v) {
    __half2 h01 = __floats2half2_rn(v.x, v.y);
    __half2 h23 = __floats2half2_rn(v.z, v.w);
    uint32_t u0 = *reinterpret_cast<uint32_t*>(&h01);
    uint32_t u1 = *reinterpret_cast<uint32_t*>(&h23);
    asm volatile("st.shared.v2.b32 [%0], {%1,%2};"
                 :: "r"(addr), "r"(u0), "r"(u1) : "memory");
}

// ===========================================================================
// L1 fp16 mma: h1 = relu(low @ w1 + b1). (R11-identical, validated)
// ===========================================================================
#define L1_APITCH 40
#define L1_BPITCH 72
#define L1_ABUFH  (64 * L1_APITCH)
#define L1_BBUFH  (32 * L1_BPITCH)

__global__ void __launch_bounds__(256)
l1_mma(const float* __restrict__ low, const float* __restrict__ w1,
       const float* __restrict__ b1, float* __restrict__ h1)
{
    __shared__ __half As[2][L1_ABUFH];
    __shared__ __half Bs[2][L1_BBUFH];

    const int tid  = threadIdx.x;
    const int wid  = tid >> 5;
    const int lane = tid & 31;
    const int g    = lane >> 2;
    const int q    = lane & 3;

    const int bm = (blockIdx.x >> 4) * 64;
    const int bn = (blockIdx.x & 15) * 64;

    const int wm = (wid >> 2) * 32;
    const int wn = (wid & 3) * 16;

    const uint32_t aBase = smem_u32(&As[0][0]);
    const uint32_t bBase = smem_u32(&Bs[0][0]);

    const int am0 = tid >> 3,  akc = tid & 7;
    const int bk0 = tid >> 4,  bnc = tid & 15;
    const float* aS = low + (size_t)(bm + am0) * 8192 + akc * 4;
    const float* bS = w1 + (size_t)bk0 * 1024 + bn + bnc * 4;
    const uint32_t aD0 = aBase + (uint32_t)(am0 * L1_APITCH + akc * 4) * 2;
    const uint32_t aD1 = aBase + (uint32_t)((am0 + 32) * L1_APITCH + akc * 4) * 2;
    const uint32_t bD0 = bBase + (uint32_t)(bk0 * L1_BPITCH + bnc * 4) * 2;
    const uint32_t bD1 = bBase + (uint32_t)((bk0 + 16) * L1_BPITCH + bnc * 4) * 2;

    float4 rA[2][2], rB[2][2];
#define L1_LDG(slot, it)                                                       \
    do {                                                                       \
        rA[slot][0] = *reinterpret_cast<const float4*>(aS + (it) * 32);        \
        rA[slot][1] = *reinterpret_cast<const float4*>(aS + 32 * 8192 + (it) * 32); \
        rB[slot][0] = *reinterpret_cast<const float4*>(bS + (size_t)(it) * 32 * 1024); \
        rB[slot][1] = *reinterpret_cast<const float4*>(bS + (size_t)((it) * 32 + 16) * 1024); \
    } while (0)

    L1_LDG(0, 0);
    L1_LDG(1, 1);

    const int mi = lane >> 3;
    const int r8 = lane & 7;
    const uint32_t aLd = aBase +
        (uint32_t)(((wm + (mi & 1) * 8 + r8) * L1_APITCH + (mi >> 1) * 8) * 2);
    const uint32_t bLd = bBase +
        (uint32_t)(((lane & 15) * L1_BPITCH + wn + (lane >> 4) * 8) * 2);

    float acc[2][2][4];
#pragma unroll
    for (int i = 0; i < 2; i++)
#pragma unroll
        for (int j = 0; j < 2; j++)
#pragma unroll
            for (int k = 0; k < 4; k++) acc[i][j][k] = 0.0f;

    for (int it = 0; it < 256; it++) {
        const int sl = it & 1;
        const uint32_t aOfs = (uint32_t)sl * (L1_ABUFH * 2);
        const uint32_t bOfs = (uint32_t)sl * (L1_BBUFH * 2);

        sts_cvt4(aD0 + aOfs, rA[sl][0]);
        sts_cvt4(aD1 + aOfs, rA[sl][1]);
        sts_cvt4(bD0 + bOfs, rB[sl][0]);
        sts_cvt4(bD1 + bOfs, rB[sl][1]);
        __syncthreads();

        if (it + 2 < 256) {
            L1_LDG(sl, it + 2);
        }

#pragma unroll
        for (int h = 0; h < 2; h++) {
            uint32_t b0, b1, b2, b3;
            ldsm_x4t(b0, b1, b2, b3,
                     bLd + bOfs + (uint32_t)(h * 16 * L1_BPITCH * 2));
#pragma unroll
            for (int mt = 0; mt < 2; mt++) {
                uint32_t a0, a1, a2, a3;
                ldsm_x4(a0, a1, a2, a3,
                        aLd + aOfs +
                        (uint32_t)((mt * 16 * L1_APITCH + h * 16) * 2));
                mma_fp16(acc[mt][0][0], acc[mt][0][1], acc[mt][0][2], acc[mt][0][3],
                         a0, a1, a2, a3, b0, b1);
                mma_fp16(acc[mt][1][0], acc[mt][1][1], acc[mt][1][2], acc[mt][1][3],
                         a0, a1, a2, a3, b2, b3);
            }
        }
        __syncthreads();
    }
#undef L1_LDG

#pragma unroll
    for (int mt = 0; mt < 2; mt++) {
#pragma unroll
        for (int h8 = 0; h8 < 2; h8++) {
            const int row = bm + wm + mt * 16 + g + h8 * 8;
#pragma unroll
            for (int nt = 0; nt < 2; nt++) {
                const int col = bn + wn + nt * 8 + 2 * q;
                float v0 = fmaxf(acc[mt][nt][2 * h8]     + b1[col],     0.0f);
                float v1 = fmaxf(acc[mt][nt][2 * h8 + 1] + b1[col + 1], 0.0f);
                *reinterpret_cast<float2*>(h1 + (size_t)row * 1024 + col) =
                    make_float2(v0, v1);
            }
        }
    }
}

// ===========================================================================
// GEMM6 fp16: R11 core + B prefetch distance 2.
// ===========================================================================
#define G6_STG    6
#define G6_PITCH  24
#define G6_TILEH  (128 * G6_PITCH)
#define G6_TILEB  (G6_TILEH * 2)
#define G6_BPITCH 136
#define G6_BBUFH  (16 * G6_BPITCH)
#define G6_BBUFB  (G6_BBUFH * 2)
#define G6_NKT    64
#define G6_SMEMB  (G6_STG * G6_TILEB + 2 * G6_BBUFB + 512)

__global__ void __launch_bounds__(256, 2)
gemm6_fp16(const __half* __restrict__ Ah,   // d2h tiled [64][512][16]
           const float* __restrict__ w6,    // fp32 [1024][131072]
           const float* __restrict__ bias,
           const float* __restrict__ low,
           float* __restrict__ out)
{
    extern __shared__ __half sm[];
    __half* Asm = sm;
    __half* Bsm = sm + G6_STG * G6_TILEH;
    float*  sbias = reinterpret_cast<float*>(sm + G6_STG * G6_TILEH + 2 * G6_BBUFH);

    const int tid  = threadIdx.x;
    const int wid  = tid >> 5;
    const int lane = tid & 31;
    const int g    = lane >> 2;
    const int q    = lane & 3;

    const int bm = blockIdx.x * 128;
    const int bn = blockIdx.y * 128;

    const int wm = (wid >> 2) * 64;
    const int wn = (wid & 3) * 32;

    if (tid < 128) sbias[tid] = bias[bn + tid];

    const uint32_t aBase = smem_u32(Asm);
    const uint32_t bBase = smem_u32(Bsm);

    // ---- A: cp.async, 6 stages, dist 5 ----
    const __half* aSrc = Ah + (size_t)bm * 16 + tid * 8;
    const uint32_t aDst = aBase + (tid >> 1) * 48 + (tid & 1) * 16;
#define G6_LOADA(s, kt) cp16_cg(aDst + (s) * G6_TILEB, aSrc + (kt) * 8192)

    G6_LOADA(0, 0); CP_COMMIT();
    G6_LOADA(1, 1); CP_COMMIT();
    G6_LOADA(2, 2); CP_COMMIT();
    G6_LOADA(3, 3); CP_COMMIT();
    G6_LOADA(4, 4); CP_COMMIT();

    // ---- B: fp32 LDG, prefetch distance 2, double-buffered smem ----
    const int bk0 = tid >> 5;
    const int bnc = tid & 31;
    const float* bS = w6 + (size_t)bk0 * NOUTCOL + bn + bnc * 4;
    const uint32_t bD0 = bBase + (uint32_t)(bk0 * G6_BPITCH + bnc * 4) * 2;
    const uint32_t bD1 = bBase + (uint32_t)((bk0 + 8) * G6_BPITCH + bnc * 4) * 2;

    float4 rb[2][2];
#define G6_LDGB(buf, kt)                                                       \
    do {                                                                       \
        rb[buf][0] = *reinterpret_cast<const float4*>(bS + (size_t)(kt) * 16 * NOUTCOL); \
        rb[buf][1] = *reinterpret_cast<const float4*>(bS + (size_t)((kt) * 16 + 8) * NOUTCOL); \
    } while (0)

    G6_LDGB(0, 0);
    G6_LDGB(1, 1);

    const int mi = lane >> 3;
    const int r8 = lane & 7;
    const uint32_t aLd = aBase +
        (uint32_t)(((wm + (mi & 1) * 8 + r8) * G6_PITCH + (mi >> 1) * 8) * 2);
    const uint32_t bLd = bBase +
        (uint32_t)(((lane & 15) * G6_BPITCH + wn + (lane >> 4) * 8) * 2);

    float acc[4][4][4];
#pragma unroll
    for (int i = 0; i < 4; i++)
#pragma unroll
        for (int j = 0; j < 4; j++)
#pragma unroll
            for (int k = 0; k < 4; k++) acc[i][j][k] = 0.0f;

    int s = 0, sl = G6_STG - 1;
    for (int kt = 0; kt < G6_NKT; kt++) {
        const int buf = kt & 1;
        const uint32_t bOfs = (uint32_t)buf * G6_BBUFB;

        // cvt + STS B(kt) from register buffer
        sts_cvt4(bD0 + bOfs, rb[buf][0]);
        sts_cvt4(bD1 + bOfs, rb[buf][1]);

        // prefetch B(kt+2) into the buffer just drained
        if (kt + 2 < G6_NKT) {
            G6_LDGB(buf, kt + 2);
        }

        CP_WAIT4();
        __syncthreads();
        if (kt + 5 < G6_NKT) {
            G6_LOADA(sl, kt + 5);
        }
        CP_COMMIT();

        const uint32_t so = (uint32_t)s * G6_TILEB;

        uint32_t bf[4][2];
        ldsm_x4t(bf[0][0], bf[0][1], bf[1][0], bf[1][1], bLd + bOfs);
        ldsm_x4t(bf[2][0], bf[2][1], bf[3][0], bf[3][1], bLd + bOfs + 32);

#pragma unroll
        for (int mt = 0; mt < 4; mt++) {
            uint32_t a0, a1, a2, a3;
            ldsm_x4(a0, a1, a2, a3, aLd + mt * (16 * G6_PITCH * 2) + so);
#pragma unroll
            for (int nt = 0; nt < 4; nt++)
                mma_fp16(acc[mt][nt][0], acc[mt][nt][1],
                         acc[mt][nt][2], acc[mt][nt][3],
                         a0, a1, a2, a3, bf[nt][0], bf[nt][1]);
        }

        s  = (s  + 1 == G6_STG) ? 0 : s  + 1;
        sl = (sl + 1 == G6_STG) ? 0 : sl + 1;
    }
#undef G6_LOADA
#undef G6_LDGB

    // ---- fused epilogue (warp-uniform t) ----
    const int t   = (bn + wn) >> 5;
    const int rem = t & 15;
    const int seg = t >> 4;
    const bool knot  = (rem == 0);
    const bool inseg = (!knot) && (t < LAST_KNOT);
    const float alpha = (float)rem * 0.0625f;
    const int segB = (seg < NL - 1) ? seg + 1 : NL - 1;

#pragma unroll
    for (int mt = 0; mt < 4; mt++) {
#pragma unroll
        for (int h = 0; h < 2; h++) {
            const int r = bm + wm + mt * 16 + g + h * 8;
            const float* lowr = low + (size_t)r * (NL * NF);
            float* outr = out + (size_t)r * NOUTCOL + bn + wn;
#pragma unroll
            for (int nt = 0; nt < 4; nt++) {
                const int f = nt * 8 + 2 * q;
                float dec0 = acc[mt][nt][2 * h]     + sbias[wn + f];
                float dec1 = acc[mt][nt][2 * h + 1] + sbias[wn + f + 1];
                float2 la = *reinterpret_cast<const float2*>(lowr + seg  * NF + f);
                float2 lb = *reinterpret_cast<const float2*>(lowr + segB * NF + f);
                float lin0 = (1.0f - alpha) * la.x + alpha * lb.x;
                float lin1 = (1.0f - alpha) * la.y + alpha * lb.y;
                float r0 = knot ? la.x : (inseg ? 0.8f * lin0 + 0.2f * dec0 : dec0);
                float r1 = knot ? la.y : (inseg ? 0.8f * lin1 + 0.2f * dec1 : dec1);
                *reinterpret_cast<float2*>(outr + f) = make_float2(r0, r1);
            }
        }
    }
}

// ===========================================================================
// Small-layer SIMT SGEMM, generalized to TM/TN in {2,4}; float2 epilogue.
// TILEDH=true stores fp16 tiled [col/16][row][16].
// ===========================================================================
template <int BM, int BN, int BK, int TM, int TN, bool RELU, bool TILEDH>
__global__ __launch_bounds__((BM / TM) * (BN / TN))
void sgemm_bias(const float* __restrict__ A, const float* __restrict__ Bm,
                const float* __restrict__ bias, void* __restrict__ Cv,
                int M, int N, int K)
{
    constexpr int THREADS = (BM / TM) * (BN / TN);
    __shared__ float As[BK][BM + 4];
    __shared__ float Bs[BK][BN];

    const int tid = threadIdx.x;
    const int bn  = blockIdx.x * BN;
    const int bm  = blockIdx.y * BM;
    const int tx  = tid % (BN / TN);
    const int ty  = tid / (BN / TN);

    float acc[TM][TN];
#pragma unroll
    for (int i = 0; i < TM; i++)
#pragma unroll
        for (int j = 0; j < TN; j++) acc[i][j] = 0.0f;

    constexpr int AV = BK / 4, AT = BM * AV;
    constexpr int BV = BN / 4, BT = BK * BV;

    for (int k0 = 0; k0 < K; k0 += BK) {
        for (int i = tid; i < AT; i += THREADS) {
            int r = i / AV, c4 = (i % AV) * 4;
            float4 v = *reinterpret_cast<const float4*>(
                A + (size_t)(bm + r) * K + k0 + c4);
            As[c4 + 0][r] = v.x; As[c4 + 1][r] = v.y;
            As[c4 + 2][r] = v.z; As[c4 + 3][r] = v.w;
        }
        for (int i = tid; i < BT; i += THREADS) {
            int r = i / BV, c4 = (i % BV) * 4;
            *reinterpret_cast<float4*>(&Bs[r][c4]) =
                *reinterpret_cast<const float4*>(
                    Bm + (size_t)(k0 + r) * N + bn + c4);
        }
        __syncthreads();

#pragma unroll
        for (int kk = 0; kk < BK; kk++) {
            float ra[TM], rb[TN];
            if constexpr (TM % 4 == 0) {
#pragma unroll
                for (int i = 0; i < TM; i += 4)
                    *reinterpret_cast<float4*>(&ra[i]) =
                        *reinterpret_cast<const float4*>(&As[kk][ty * TM + i]);
            } else {
#pragma unroll
                for (int i = 0; i < TM; i += 2)
                    *reinterpret_cast<float2*>(&ra[i]) =
                        *reinterpret_cast<const float2*>(&As[kk][ty * TM + i]);
            }
            if constexpr (TN % 4 == 0) {
#pragma unroll
                for (int j = 0; j < TN; j += 4)
                    *reinterpret_cast<float4*>(&rb[j]) =
                        *reinterpret_cast<const float4*>(&Bs[kk][tx * TN + j]);
            } else {
#pragma unroll
                for (int j = 0; j < TN; j += 2)
                    *reinterpret_cast<float2*>(&rb[j]) =
                        *reinterpret_cast<const float2*>(&Bs[kk][tx * TN + j]);
            }
#pragma unroll
            for (int i = 0; i < TM; i++)
#pragma unroll
                for (int j = 0; j < TN; j++)
                    acc[i][j] = fmaf(ra[i], rb[j], acc[i][j]);
        }
        __syncthreads();
    }

#pragma unroll
    for (int i = 0; i < TM; i++) {
        int row = bm + ty * TM + i;
#pragma unroll
        for (int j = 0; j < TN; j += 2) {
            int col = bn + tx * TN + j;
            float v0 = acc[i][j + 0] + bias[col + 0];
            float v1 = acc[i][j + 1] + bias[col + 1];
            if (RELU) {
                v0 = fmaxf(v0, 0.0f);
                v1 = fmaxf(v1, 0.0f);
            }
            if (TILEDH) {
                __half* C = (__half*)Cv;
                __half* p = C + ((size_t)(col >> 4) * M + row) * 16 + (col & 15);
                *reinterpret_cast<__half2*>(p) = __floats2half2_rn(v0, v1);
            } else {
                float* C = (float*)Cv;
                *reinterpret_cast<float2*>(C + (size_t)row * N + col) =
                    make_float2(v0, v1);
            }
        }
    }
}

// ---------------------------------------------------------------------------
extern "C" void kernel_launch(void* const* d_in, const int* in_sizes, int n_in,
                              void* d_out, int out_size)
{
    const float* low = (const float*)d_in[0];
    const float* w1  = (const float*)d_in[1];
    const float* b1  = (const float*)d_in[2];
    const float* w2  = (const float*)d_in[3];
    const float* b2  = (const float*)d_in[4];
    const float* w3  = (const float*)d_in[5];
    const float* b3  = (const float*)d_in[6];
    const float* w4  = (const float*)d_in[7];
    const float* b4  = (const float*)d_in[8];
    const float* w5  = (const float*)d_in[9];
    const float* b5  = (const float*)d_in[10];
    const float* w6  = (const float*)d_in[11];
    const float* b6  = (const float*)d_in[12];
    float* out = (float*)d_out;

    float  *h1, *h2, *fe, *d1;
    __half *d2h;
    cudaGetSymbolAddress((void**)&h1,  g_h1);
    cudaGetSymbolAddress((void**)&h2,  g_h2);
    cudaGetSymbolAddress((void**)&fe,  g_fe);
    cudaGetSymbolAddress((void**)&d1,  g_d1);
    cudaGetSymbolAddress((void**)&d2h, g_d2h);

    cudaFuncSetAttribute(gemm6_fp16,
                         cudaFuncAttributeMaxDynamicSharedMemorySize, G6_SMEMB);

    // Launch 1: L1 via fp16 mma
    l1_mma<<<128, 256>>>(low, w1, b1, h1);
    // Launch 2: L2 (512x512x1024), 64x32 tiles -> 128 CTAs
    sgemm_bias<64, 32, 16, 4, 2, true, false>
        <<<dim3(512 / 32, 512 / 64), 256>>>(h1, w2, b2, h2, 512, 512, 1024);
    // Launch 3: L3 (512x256x512), 32x32 tiles -> 128 CTAs
    sgemm_bias<32, 32, 16, 2, 2, false, false>
        <<<dim3(256 / 32, 512 / 32), 256>>>(h2, w3, b3, fe, 512, 256, 512);
    // Launch 4: L4 (512x512x256), 64x32 tiles -> 128 CTAs
    sgemm_bias<64, 32, 16, 4, 2, true, false>
        <<<dim3(512 / 32, 512 / 64), 256>>>(fe, w4, b4, d1, 512, 512, 256);
    // Launch 5: L5 (512x1024x512), 64x64 tiles -> 128 CTAs, fp16 tiled out
    sgemm_bias<64, 64, 16, 4, 4, true, true>
        <<<dim3(1024 / 64, 512 / 64), 256>>>(d1, w5, b5, d2h, 512, 1024, 512);
    // Launch 6: GEMM6
    gemm6_fp16<<<dim3(4, NOUTCOL / 128), 256, G6_SMEMB>>>(d2h, w6, b6, low, out);
}

// round 13
// speedup vs baseline: 2.4475x; 1.0063x over previous
#include <cuda_runtime.h>
#include <cuda_fp16.h>
#include <cstdint>

// ---------------------------------------------------------------------------
// ConstrainedEnhancementModel on GB300 (ptxas target sm_103: no 'a' features).
// R13 = R12 (795us) with L1-L5 fused into one persistent 128-CTA kernel
// using a global generation barrier between phases (all phases tile to
// exactly 128 CTAs; co-residency guaranteed). gemm6 unchanged.
// ---------------------------------------------------------------------------

#define NB   512
#define NL   256
#define NF   32
#define NH   4096
#define NOUTCOL (NH * NF)          // 131072
#define LAST_KNOT ((NL - 1) * 16)  // 4080
#define NBLK 128                   // persistent grid size

__device__ float  g_h1[512 * 1024];
__device__ float  g_h2[512 * 512];
__device__ float  g_fe[512 * 256];
__device__ float  g_d1[512 * 512];
__device__ __half g_d2h[512 * 1024];                // tiled [kt][m][16]

// grid barrier state (generation-based; survives graph replays)
__device__ volatile unsigned g_bar_gen;
__device__ unsigned g_bar_cnt;

__device__ __forceinline__ void grid_sync() {
    __syncthreads();
    if (threadIdx.x == 0) {
        const unsigned gen = g_bar_gen;
        __threadfence();
        const unsigned t = atomicAdd(&g_bar_cnt, 1);
        if (t == NBLK - 1) {
            g_bar_cnt = 0;
            __threadfence();
            g_bar_gen = gen + 1;
        } else {
            while (g_bar_gen == gen) { }
            __threadfence();
        }
    }
    __syncthreads();
}

// ===========================================================================
// helpers
// ===========================================================================
__device__ __forceinline__ uint32_t smem_u32(const void* p) {
    uint32_t a;
    asm("{ .reg .u64 t; cvta.to.shared.u64 t, %1; cvt.u32.u64 %0, t; }"
        : "=r"(a) : "l"(p));
    return a;
}
__device__ __forceinline__ void cp16_cg(uint32_t dst, const void* src) {
    asm volatile("cp.async.cg.shared.global [%0], [%1], 16;"
                 :: "r"(dst), "l"(src) : "memory");
}
#define CP_COMMIT() asm volatile("cp.async.commit_group;" ::: "memory")
#define CP_WAIT4()  asm volatile("cp.async.wait_group 4;" ::: "memory")

__device__ __forceinline__ void ldsm_x4(uint32_t& r0, uint32_t& r1,
                                        uint32_t& r2, uint32_t& r3, uint32_t addr) {
    asm volatile("ldmatrix.sync.aligned.m8n8.x4.shared.b16 {%0,%1,%2,%3}, [%4];"
                 : "=r"(r0), "=r"(r1), "=r"(r2), "=r"(r3) : "r"(addr));
}
__device__ __forceinline__ void ldsm_x4t(uint32_t& r0, uint32_t& r1,
                                         uint32_t& r2, uint32_t& r3, uint32_t addr) {
    asm volatile("ldmatrix.sync.aligned.m8n8.x4.trans.shared.b16 {%0,%1,%2,%3}, [%4];"
                 : "=r"(r0), "=r"(r1), "=r"(r2), "=r"(r3) : "r"(addr));
}

__device__ __forceinline__ void mma_fp16(float& c0, float& c1, float& c2, float& c3,
                                         uint32_t a0, uint32_t a1, uint32_t a2, uint32_t a3,
                                         uint32_t b0, uint32_t b1) {
    asm volatile(
        "mma.sync.aligned.m16n8k16.row.col.f32.f16.f16.f32 "
        "{%0,%1,%2,%3}, {%4,%5,%6,%7}, {%8,%9}, {%0,%1,%2,%3};"
        : "+f"(c0), "+f"(c1), "+f"(c2), "+f"(c3)
        : "r"(a0), "r"(a1), "r"(a2), "r"(a3), "r"(b0), "r"(b1));
}

__device__ __forceinline__ void sts_cvt4(uint32_t addr, float4 v) {
    __half2 h01 = __floats2half2_rn(v.x, v.y);
    __half2 h23 = __floats2half2_rn(v.z, v.w);
    uint32_t u0 = *reinterpret_cast<uint32_t*>(&h01);
    uint32_t u1 = *reinterpret_cast<uint32_t*>(&h23);
    asm volatile("st.shared.v2.b32 [%0], {%1,%2};"
                 :: "r"(addr), "r"(u0), "r"(u1) : "memory");
}

// ===========================================================================
// Phase bodies (device functions over a shared scratch buffer)
// ===========================================================================
#define L1_APITCH 40
#define L1_BPITCH 72
#define L1_ABUFH  (64 * L1_APITCH)   // 2560 halfs per buffer
#define L1_BBUFH  (32 * L1_BPITCH)   // 2304 halfs per buffer
// L1 smem: 2*(2560+2304)*2 = 19456 B

__device__ void l1_phase(const float* __restrict__ low,
                         const float* __restrict__ w1,
                         const float* __restrict__ b1,
                         float* __restrict__ h1,
                         char* smbuf, int bid)
{
    __half* As = reinterpret_cast<__half*>(smbuf);                 // 2 buffers
    __half* Bs = reinterpret_cast<__half*>(smbuf + 2 * L1_ABUFH * 2);

    const int tid  = threadIdx.x;
    const int wid  = tid >> 5;
    const int lane = tid & 31;
    const int g    = lane >> 2;
    const int q    = lane & 3;

    const int bm = (bid >> 4) * 64;
    const int bn = (bid & 15) * 64;

    const int wm = (wid >> 2) * 32;
    const int wn = (wid & 3) * 16;

    const uint32_t aBase = smem_u32(As);
    const uint32_t bBase = smem_u32(Bs);

    const int am0 = tid >> 3,  akc = tid & 7;
    const int bk0 = tid >> 4,  bnc = tid & 15;
    const float* aS = low + (size_t)(bm + am0) * 8192 + akc * 4;
    const float* bS = w1 + (size_t)bk0 * 1024 + bn + bnc * 4;
    const uint32_t aD0 = aBase + (uint32_t)(am0 * L1_APITCH + akc * 4) * 2;
    const uint32_t aD1 = aBase + (uint32_t)((am0 + 32) * L1_APITCH + akc * 4) * 2;
    const uint32_t bD0 = bBase + (uint32_t)(bk0 * L1_BPITCH + bnc * 4) * 2;
    const uint32_t bD1 = bBase + (uint32_t)((bk0 + 16) * L1_BPITCH + bnc * 4) * 2;

    float4 rA[2][2], rB[2][2];
#define L1_LDG(slot, it)                                                       \
    do {                                                                       \
        rA[slot][0] = *reinterpret_cast<const float4*>(aS + (it) * 32);        \
        rA[slot][1] = *reinterpret_cast<const float4*>(aS + 32 * 8192 + (it) * 32); \
        rB[slot][0] = *reinterpret_cast<const float4*>(bS + (size_t)(it) * 32 * 1024); \
        rB[slot][1] = *reinterpret_cast<const float4*>(bS + (size_t)((it) * 32 + 16) * 1024); \
    } while (0)

    L1_LDG(0, 0);
    L1_LDG(1, 1);

    const int mi = lane >> 3;
    const int r8 = lane & 7;
    const uint32_t aLd = aBase +
        (uint32_t)(((wm + (mi & 1) * 8 + r8) * L1_APITCH + (mi >> 1) * 8) * 2);
    const uint32_t bLd = bBase +
        (uint32_t)(((lane & 15) * L1_BPITCH + wn + (lane >> 4) * 8) * 2);

    float acc[2][2][4];
#pragma unroll
    for (int i = 0; i < 2; i++)
#pragma unroll
        for (int j = 0; j < 2; j++)
#pragma unroll
            for (int k = 0; k < 4; k++) acc[i][j][k] = 0.0f;

    for (int it = 0; it < 256; it++) {
        const int sl = it & 1;
        const uint32_t aOfs = (uint32_t)sl * (L1_ABUFH * 2);
        const uint32_t bOfs = (uint32_t)sl * (L1_BBUFH * 2);

        sts_cvt4(aD0 + aOfs, rA[sl][0]);
        sts_cvt4(aD1 + aOfs, rA[sl][1]);
        sts_cvt4(bD0 + bOfs, rB[sl][0]);
        sts_cvt4(bD1 + bOfs, rB[sl][1]);
        __syncthreads();

        if (it + 2 < 256) {
            L1_LDG(sl, it + 2);
        }

#pragma unroll
        for (int h = 0; h < 2; h++) {
            uint32_t b0, b1r, b2, b3;
            ldsm_x4t(b0, b1r, b2, b3,
                     bLd + bOfs + (uint32_t)(h * 16 * L1_BPITCH * 2));
#pragma unroll
            for (int mt = 0; mt < 2; mt++) {
                uint32_t a0, a1, a2, a3;
                ldsm_x4(a0, a1, a2, a3,
                        aLd + aOfs +
                        (uint32_t)((mt * 16 * L1_APITCH + h * 16) * 2));
                mma_fp16(acc[mt][0][0], acc[mt][0][1], acc[mt][0][2], acc[mt][0][3],
                         a0, a1, a2, a3, b0, b1r);
                mma_fp16(acc[mt][1][0], acc[mt][1][1], acc[mt][1][2], acc[mt][1][3],
                         a0, a1, a2, a3, b2, b3);
            }
        }
        __syncthreads();
    }
#undef L1_LDG

#pragma unroll
    for (int mt = 0; mt < 2; mt++) {
#pragma unroll
        for (int h8 = 0; h8 < 2; h8++) {
            const int row = bm + wm + mt * 16 + g + h8 * 8;
#pragma unroll
            for (int nt = 0; nt < 2; nt++) {
                const int col = bn + wn + nt * 8 + 2 * q;
                float v0 = fmaxf(acc[mt][nt][2 * h8]     + b1[col],     0.0f);
                float v1 = fmaxf(acc[mt][nt][2 * h8 + 1] + b1[col + 1], 0.0f);
                *reinterpret_cast<float2*>(h1 + (size_t)row * 1024 + col) =
                    make_float2(v0, v1);
            }
        }
    }
}

// SIMT sgemm phase (tiles = exactly 128 blocks). TILEDH -> fp16 [col/16][row][16].
template <int BM, int BN, int BK, int TM, int TN, bool RELU, bool TILEDH>
__device__ void sgemm_phase(const float* __restrict__ A,
                            const float* __restrict__ Bm,
                            const float* __restrict__ bias,
                            void* __restrict__ Cv,
                            int M, int N, int K, char* smbuf, int bid)
{
    constexpr int THREADS = 256;
    float (*As)[BM + 4] = reinterpret_cast<float(*)[BM + 4]>(smbuf);
    float (*Bs)[BN] = reinterpret_cast<float(*)[BN]>(smbuf + BK * (BM + 4) * 4);

    const int tid = threadIdx.x;
    const int gw  = N / BN;
    const int bn  = (bid % gw) * BN;
    const int bm  = (bid / gw) * BM;
    const int tx  = tid % (BN / TN);
    const int ty  = tid / (BN / TN);

    float acc[TM][TN];
#pragma unroll
    for (int i = 0; i < TM; i++)
#pragma unroll
        for (int j = 0; j < TN; j++) acc[i][j] = 0.0f;

    constexpr int AV = BK / 4, AT = BM * AV;
    constexpr int BV = BN / 4, BT = BK * BV;

    for (int k0 = 0; k0 < K; k0 += BK) {
        for (int i = tid; i < AT; i += THREADS) {
            int r = i / AV, c4 = (i % AV) * 4;
            float4 v = *reinterpret_cast<const float4*>(
                A + (size_t)(bm + r) * K + k0 + c4);
            As[c4 + 0][r] = v.x; As[c4 + 1][r] = v.y;
            As[c4 + 2][r] = v.z; As[c4 + 3][r] = v.w;
        }
        for (int i = tid; i < BT; i += THREADS) {
            int r = i / BV, c4 = (i % BV) * 4;
            *reinterpret_cast<float4*>(&Bs[r][c4]) =
                *reinterpret_cast<const float4*>(
                    Bm + (size_t)(k0 + r) * N + bn + c4);
        }
        __syncthreads();

#pragma unroll
        for (int kk = 0; kk < BK; kk++) {
            float ra[TM], rb[TN];
            if constexpr (TM % 4 == 0) {
#pragma unroll
                for (int i = 0; i < TM; i += 4)
                    *reinterpret_cast<float4*>(&ra[i]) =
                        *reinterpret_cast<const float4*>(&As[kk][ty * TM + i]);
            } else {
#pragma unroll
                for (int i = 0; i < TM; i += 2)
                    *reinterpret_cast<float2*>(&ra[i]) =
                        *reinterpret_cast<const float2*>(&As[kk][ty * TM + i]);
            }
            if constexpr (TN % 4 == 0) {
#pragma unroll
                for (int j = 0; j < TN; j += 4)
                    *reinterpret_cast<float4*>(&rb[j]) =
                        *reinterpret_cast<const float4*>(&Bs[kk][tx * TN + j]);
            } else {
#pragma unroll
                for (int j = 0; j < TN; j += 2)
                    *reinterpret_cast<float2*>(&rb[j]) =
                        *reinterpret_cast<const float2*>(&Bs[kk][tx * TN + j]);
            }
#pragma unroll
            for (int i = 0; i < TM; i++)
#pragma unroll
                for (int j = 0; j < TN; j++)
                    acc[i][j] = fmaf(ra[i], rb[j], acc[i][j]);
        }
        __syncthreads();
    }

#pragma unroll
    for (int i = 0; i < TM; i++) {
        int row = bm + ty * TM + i;
#pragma unroll
        for (int j = 0; j < TN; j += 2) {
            int col = bn + tx * TN + j;
            float v0 = acc[i][j + 0] + bias[col + 0];
            float v1 = acc[i][j + 1] + bias[col + 1];
            if (RELU) {
                v0 = fmaxf(v0, 0.0f);
                v1 = fmaxf(v1, 0.0f);
            }
            if (TILEDH) {
                __half* C = (__half*)Cv;
                __half* p = C + ((size_t)(col >> 4) * M + row) * 16 + (col & 15);
                *reinterpret_cast<__half2*>(p) = __floats2half2_rn(v0, v1);
            } else {
                float* C = (float*)Cv;
                *reinterpret_cast<float2*>(C + (size_t)row * N + col) =
                    make_float2(v0, v1);
            }
        }
    }
}

// ===========================================================================
// Fused preamble: L1 (fp16 mma) -> L2 -> L3 -> L4 -> L5, one persistent
// 128-CTA kernel with grid_sync between phases.
// ===========================================================================
__global__ void __launch_bounds__(256)
fused_pre(const float* __restrict__ low,
          const float* __restrict__ w1, const float* __restrict__ b1,
          const float* __restrict__ w2, const float* __restrict__ b2,
          const float* __restrict__ w3, const float* __restrict__ b3,
          const float* __restrict__ w4, const float* __restrict__ b4,
          const float* __restrict__ w5, const float* __restrict__ b5,
          float* __restrict__ h1, float* __restrict__ h2,
          float* __restrict__ fe, float* __restrict__ d1,
          __half* __restrict__ d2h)
{
    __shared__ __align__(16) char smbuf[19456];
    const int bid = blockIdx.x;

    l1_phase(low, w1, b1, h1, smbuf, bid);
    grid_sync();
    sgemm_phase<64, 32, 16, 4, 2, true, false>(h1, w2, b2, h2, 512, 512, 1024,
                                               smbuf, bid);
    grid_sync();
    sgemm_phase<32, 32, 16, 2, 2, false, false>(h2, w3, b3, fe, 512, 256, 512,
                                                smbuf, bid);
    grid_sync();
    sgemm_phase<64, 32, 16, 4, 2, true, false>(fe, w4, b4, d1, 512, 512, 256,
                                               smbuf, bid);
    grid_sync();
    sgemm_phase<64, 64, 16, 4, 4, true, true>(d1, w5, b5, d2h, 512, 1024, 512,
                                              smbuf, bid);
}

// ===========================================================================
// GEMM6 fp16 (R12-identical): A cp.async 6 stages dist 5; B inline fp32->fp16
// with register prefetch distance 2; ldmatrix frags; fused epilogue.
// ===========================================================================
#define G6_STG    6
#define G6_PITCH  24
#define G6_TILEH  (128 * G6_PITCH)
#define G6_TILEB  (G6_TILEH * 2)
#define G6_BPITCH 136
#define G6_BBUFH  (16 * G6_BPITCH)
#define G6_BBUFB  (G6_BBUFH * 2)
#define G6_NKT    64
#define G6_SMEMB  (G6_STG * G6_TILEB + 2 * G6_BBUFB + 512)

__global__ void __launch_bounds__(256, 2)
gemm6_fp16(const __half* __restrict__ Ah,
           const float* __restrict__ w6,
           const float* __restrict__ bias,
           const float* __restrict__ low,
           float* __restrict__ out)
{
    extern __shared__ __half sm[];
    __half* Asm = sm;
    __half* Bsm = sm + G6_STG * G6_TILEH;
    float*  sbias = reinterpret_cast<float*>(sm + G6_STG * G6_TILEH + 2 * G6_BBUFH);

    const int tid  = threadIdx.x;
    const int wid  = tid >> 5;
    const int lane = tid & 31;
    const int g    = lane >> 2;
    const int q    = lane & 3;

    const int bm = blockIdx.x * 128;
    const int bn = blockIdx.y * 128;

    const int wm = (wid >> 2) * 64;
    const int wn = (wid & 3) * 32;

    if (tid < 128) sbias[tid] = bias[bn + tid];

    const uint32_t aBase = smem_u32(Asm);
    const uint32_t bBase = smem_u32(Bsm);

    const __half* aSrc = Ah + (size_t)bm * 16 + tid * 8;
    const uint32_t aDst = aBase + (tid >> 1) * 48 + (tid & 1) * 16;
#define G6_LOADA(s, kt) cp16_cg(aDst + (s) * G6_TILEB, aSrc + (kt) * 8192)

    G6_LOADA(0, 0); CP_COMMIT();
    G6_LOADA(1, 1); CP_COMMIT();
    G6_LOADA(2, 2); CP_COMMIT();
    G6_LOADA(3, 3); CP_COMMIT();
    G6_LOADA(4, 4); CP_COMMIT();

    const int bk0 = tid >> 5;
    const int bnc = tid & 31;
    const float* bS = w6 + (size_t)bk0 * NOUTCOL + bn + bnc * 4;
    const uint32_t bD0 = bBase + (uint32_t)(bk0 * G6_BPITCH + bnc * 4) * 2;
    const uint32_t bD1 = bBase + (uint32_t)((bk0 + 8) * G6_BPITCH + bnc * 4) * 2;

    float4 rb[2][2];
#define G6_LDGB(buf, kt)                                                       \
    do {                                                                       \
        rb[buf][0] = *reinterpret_cast<const float4*>(bS + (size_t)(kt) * 16 * NOUTCOL); \
        rb[buf][1] = *reinterpret_cast<const float4*>(bS + (size_t)((kt) * 16 + 8) * NOUTCOL); \
    } while (0)

    G6_LDGB(0, 0);
    G6_LDGB(1, 1);

    const int mi = lane >> 3;
    const int r8 = lane & 7;
    const uint32_t aLd = aBase +
        (uint32_t)(((wm + (mi & 1) * 8 + r8) * G6_PITCH + (mi >> 1) * 8) * 2);
    const uint32_t bLd = bBase +
        (uint32_t)(((lane & 15) * G6_BPITCH + wn + (lane >> 4) * 8) * 2);

    float acc[4][4][4];
#pragma unroll
    for (int i = 0; i < 4; i++)
#pragma unroll
        for (int j = 0; j < 4; j++)
#pragma unroll
            for (int k = 0; k < 4; k++) acc[i][j][k] = 0.0f;

    int s = 0, sl = G6_STG - 1;
    for (int kt = 0; kt < G6_NKT; kt++) {
        const int buf = kt & 1;
        const uint32_t bOfs = (uint32_t)buf * G6_BBUFB;

        sts_cvt4(bD0 + bOfs, rb[buf][0]);
        sts_cvt4(bD1 + bOfs, rb[buf][1]);

        if (kt + 2 < G6_NKT) {
            G6_LDGB(buf, kt + 2);
        }

        CP_WAIT4();
        __syncthreads();
        if (kt + 5 < G6_NKT) {
            G6_LOADA(sl, kt + 5);
        }
        CP_COMMIT();

        const uint32_t so = (uint32_t)s * G6_TILEB;

        uint32_t bf[4][2];
        ldsm_x4t(bf[0][0], bf[0][1], bf[1][0], bf[1][1], bLd + bOfs);
        ldsm_x4t(bf[2][0], bf[2][1], bf[3][0], bf[3][1], bLd + bOfs + 32);

#pragma unroll
        for (int mt = 0; mt < 4; mt++) {
            uint32_t a0, a1, a2, a3;
            ldsm_x4(a0, a1, a2, a3, aLd + mt * (16 * G6_PITCH * 2) + so);
#pragma unroll
            for (int nt = 0; nt < 4; nt++)
                mma_fp16(acc[mt][nt][0], acc[mt][nt][1],
                         acc[mt][nt][2], acc[mt][nt][3],
                         a0, a1, a2, a3, bf[nt][0], bf[nt][1]);
        }

        s  = (s  + 1 == G6_STG) ? 0 : s  + 1;
        sl = (sl + 1 == G6_STG) ? 0 : sl + 1;
    }
#undef G6_LOADA
#undef G6_LDGB

    const int t   = (bn + wn) >> 5;
    const int rem = t & 15;
    const int seg = t >> 4;
    const bool knot  = (rem == 0);
    const bool inseg = (!knot) && (t < LAST_KNOT);
    const float alpha = (float)rem * 0.0625f;
    const int segB = (seg < NL - 1) ? seg + 1 : NL - 1;

#pragma unroll
    for (int mt = 0; mt < 4; mt++) {
#pragma unroll
        for (int h = 0; h < 2; h++) {
            const int r = bm + wm + mt * 16 + g + h * 8;
            const float* lowr = low + (size_t)r * (NL * NF);
            float* outr = out + (size_t)r * NOUTCOL + bn + wn;
#pragma unroll
            for (int nt = 0; nt < 4; nt++) {
                const int f = nt * 8 + 2 * q;
                float dec0 = acc[mt][nt][2 * h]     + sbias[wn + f];
                float dec1 = acc[mt][nt][2 * h + 1] + sbias[wn + f + 1];
                float2 la = *reinterpret_cast<const float2*>(lowr + seg  * NF + f);
                float2 lb = *reinterpret_cast<const float2*>(lowr + segB * NF + f);
                float lin0 = (1.0f - alpha) * la.x + alpha * lb.x;
                float lin1 = (1.0f - alpha) * la.y + alpha * lb.y;
                float r0 = knot ? la.x : (inseg ? 0.8f * lin0 + 0.2f * dec0 : dec0);
                float r1 = knot ? la.y : (inseg ? 0.8f * lin1 + 0.2f * dec1 : dec1);
                *reinterpret_cast<float2*>(outr + f) = make_float2(r0, r1);
            }
        }
    }
}

// ---------------------------------------------------------------------------
extern "C" void kernel_launch(void* const* d_in, const int* in_sizes, int n_in,
                              void* d_out, int out_size)
{
    const float* low = (const float*)d_in[0];
    const float* w1  = (const float*)d_in[1];
    const float* b1  = (const float*)d_in[2];
    const float* w2  = (const float*)d_in[3];
    const float* b2  = (const float*)d_in[4];
    const float* w3  = (const float*)d_in[5];
    const float* b3  = (const float*)d_in[6];
    const float* w4  = (const float*)d_in[7];
    const float* b4  = (const float*)d_in[8];
    const float* w5  = (const float*)d_in[9];
    const float* b5  = (const float*)d_in[10];
    const float* w6  = (const float*)d_in[11];
    const float* b6  = (const float*)d_in[12];
    float* out = (float*)d_out;

    float  *h1, *h2, *fe, *d1;
    __half *d2h;
    cudaGetSymbolAddress((void**)&h1,  g_h1);
    cudaGetSymbolAddress((void**)&h2,  g_h2);
    cudaGetSymbolAddress((void**)&fe,  g_fe);
    cudaGetSymbolAddress((void**)&d1,  g_d1);
    cudaGetSymbolAddress((void**)&d2h, g_d2h);

    cudaFuncSetAttribute(gemm6_fp16,
                         cudaFuncAttributeMaxDynamicSharedMemorySize, G6_SMEMB);

    // Launch 1: fused L1..L5 (persistent 128 CTAs, grid_sync between phases)
    fused_pre<<<NBLK, 256>>>(low, w1, b1, w2, b2, w3, b3, w4, b4, w5, b5,
                             h1, h2, fe, d1, d2h);
    // Launch 2: GEMM6
    gemm6_fp16<<<dim3(4, NOUTCOL / 128), 256, G6_SMEMB>>>(d2h, w6, b6, low, out);
}